// round 1
// baseline (speedup 1.0000x reference)
#include <cuda_runtime.h>
#include <math.h>

#define B_  2
#define T_  2048
#define D_  2048
#define H_  16
#define KV_ 4
#define HD_ 128
#define M_  (B_*T_)   // 4096
#define KVD_ (KV_*HD_) // 512

// ---------------- scratch (static device globals; no allocations) ----------
__device__ float g_Q[M_ * D_];      // (b*T+t, h*HD+d)
__device__ float g_K[M_ * KVD_];    // (b*T+t, g*HD+d)
__device__ float g_V[M_ * KVD_];
__device__ float g_O[M_ * D_];      // attention output, (b,t,H*HD)

// ---------------- SGEMM: C[m,n] = sum_k A[m,k] * W[n,k]  (both K-major) ----
// BM=BN=128, BK=16, 256 threads, 8x8 microtile per thread.
__global__ __launch_bounds__(256) void sgemm_nt(
    const float* __restrict__ A, const float* __restrict__ W,
    float* __restrict__ C, int M, int N, int K)
{
    __shared__ float As[16][128];
    __shared__ float Bs[16][128];

    const int tid = threadIdx.x;
    const int bm = blockIdx.y * 128;
    const int bn = blockIdx.x * 128;
    const int tx = tid & 15;
    const int ty = tid >> 4;
    const int lr = tid >> 2;         // 0..63
    const int lc = (tid & 3) << 2;   // 0,4,8,12

    float acc[8][8];
    #pragma unroll
    for (int i = 0; i < 8; i++)
        #pragma unroll
        for (int j = 0; j < 8; j++) acc[i][j] = 0.f;

    for (int k0 = 0; k0 < K; k0 += 16) {
        #pragma unroll
        for (int i = 0; i < 2; i++) {
            int r = lr + i * 64;
            float4 a = *(const float4*)(A + (size_t)(bm + r) * K + k0 + lc);
            As[lc+0][r] = a.x; As[lc+1][r] = a.y; As[lc+2][r] = a.z; As[lc+3][r] = a.w;
            float4 b = *(const float4*)(W + (size_t)(bn + r) * K + k0 + lc);
            Bs[lc+0][r] = b.x; Bs[lc+1][r] = b.y; Bs[lc+2][r] = b.z; Bs[lc+3][r] = b.w;
        }
        __syncthreads();
        #pragma unroll
        for (int kk = 0; kk < 16; kk++) {
            float ra[8], rb[8];
            *(float4*)(ra)   = *(const float4*)&As[kk][ty*8];
            *(float4*)(ra+4) = *(const float4*)&As[kk][ty*8+4];
            *(float4*)(rb)   = *(const float4*)&Bs[kk][tx*8];
            *(float4*)(rb+4) = *(const float4*)&Bs[kk][tx*8+4];
            #pragma unroll
            for (int i = 0; i < 8; i++)
                #pragma unroll
                for (int j = 0; j < 8; j++)
                    acc[i][j] += ra[i] * rb[j];
        }
        __syncthreads();
    }

    #pragma unroll
    for (int i = 0; i < 8; i++) {
        int row = bm + ty*8 + i;
        float* cp = C + (size_t)row * N + bn + tx*8;
        *(float4*)(cp)   = make_float4(acc[i][0], acc[i][1], acc[i][2], acc[i][3]);
        *(float4*)(cp+4) = make_float4(acc[i][4], acc[i][5], acc[i][6], acc[i][7]);
    }
}

// ---------------- RoPE (in-place) ------------------------------------------
__global__ void rope_kernel(float* __restrict__ X, int nheads, int total)
{
    int idx = blockIdx.x * blockDim.x + threadIdx.x;
    if (idx >= total) return;
    int j = idx & 63;                     // 0..63 (pair index)
    int h = (idx >> 6) % nheads;
    int m = idx / (64 * nheads);          // row (b*T + t)
    int t = m & (T_ - 1);

    float expo = -((float)(2 * j) / (float)HD_);
    float inv = powf(10000.0f, expo);
    float ang = (float)t * inv;
    float s, c;
    sincosf(ang, &s, &c);

    float* row = X + (size_t)m * (nheads * HD_) + h * HD_;
    float x1 = row[j], x2 = row[j + 64];
    row[j]      = x1 * c - x2 * s;
    row[j + 64] = x2 * c + x1 * s;
}

// ---------------- fp32 flash attention --------------------------------------
// Block = (b, h, q-tile of 64 rows). 256 threads. KV tile = 64.
// Smem: Qt[128][64], Kt[128][64], Vs[64][128], St[64][68], stats.
#define FA_SMEM_FLOATS (128*64 + 128*64 + 64*128 + 64*68 + 64*3 + 64*4*2)
#define FA_SMEM_BYTES  (FA_SMEM_FLOATS * 4)

__global__ __launch_bounds__(256) void flash_attn(
    const float* __restrict__ Q, const float* __restrict__ Kg,
    const float* __restrict__ Vg, float* __restrict__ O)
{
    extern __shared__ float sm[];
    float* Qt   = sm;                    // [d][r]  128x64
    float* Kt   = Qt + 128*64;           // [d][s]  128x64
    float* Vs   = Kt + 128*64;           // [s][d]  64x128
    float* St   = Vs + 64*128;           // [s][r]  64x68 (pad 4 for alignment)
    float* m_s  = St + 64*68;
    float* l_s  = m_s + 64;
    float* rs_s = l_s + 64;
    float* pmax = rs_s + 64;             // [4][64]
    float* psum = pmax + 4*64;           // [4][64]

    const int tid = threadIdx.x;
    const int qt  = blockIdx.x;
    const int h   = blockIdx.y;
    const int b   = blockIdx.z;
    const int g   = h >> 2;              // n_rep = 4
    const int q0  = qt * 64;
    const int tx  = tid & 15;
    const int ty  = tid >> 4;
    const float scale = 0.08838834764831845f; // 1/sqrt(128)

    // Load + transpose + pre-scale Q tile
    #pragma unroll
    for (int it = 0; it < 8; it++) {
        int lin = tid + it * 256;        // 0..2047 over (r, c4)
        int c4 = lin & 31;
        int r  = lin >> 5;
        float4 v = *(const float4*)(Q + (size_t)(b*T_ + q0 + r) * D_ + h*HD_ + c4*4);
        int d = c4 * 4;
        Qt[(d+0)*64 + r] = v.x * scale;
        Qt[(d+1)*64 + r] = v.y * scale;
        Qt[(d+2)*64 + r] = v.z * scale;
        Qt[(d+3)*64 + r] = v.w * scale;
    }
    if (tid < 64) { m_s[tid] = -INFINITY; l_s[tid] = 0.f; }

    float acc[4][8];
    #pragma unroll
    for (int i = 0; i < 4; i++)
        #pragma unroll
        for (int j = 0; j < 8; j++) acc[i][j] = 0.f;
    __syncthreads();

    for (int s0 = 0; s0 < T_; s0 += 64) {
        // Load K (transposed) and V tiles
        #pragma unroll
        for (int it = 0; it < 8; it++) {
            int lin = tid + it * 256;
            int c4 = lin & 31;
            int r  = lin >> 5;
            const size_t base = (size_t)(b*T_ + s0 + r) * KVD_ + g*HD_ + c4*4;
            float4 kv = *(const float4*)(Kg + base);
            int d = c4 * 4;
            Kt[(d+0)*64 + r] = kv.x;
            Kt[(d+1)*64 + r] = kv.y;
            Kt[(d+2)*64 + r] = kv.z;
            Kt[(d+3)*64 + r] = kv.w;
            *(float4*)&Vs[r*128 + d] = *(const float4*)(Vg + base);
        }
        __syncthreads();

        // S = (Q*scale) K^T : thread -> S[ty*4+i][tx*4+j]
        float sacc[4][4];
        #pragma unroll
        for (int i = 0; i < 4; i++)
            #pragma unroll
            for (int j = 0; j < 4; j++) sacc[i][j] = 0.f;

        #pragma unroll 8
        for (int k = 0; k < 128; k++) {
            float4 ra = *(const float4*)&Qt[k*64 + ty*4];
            float4 rb = *(const float4*)&Kt[k*64 + tx*4];
            float A0 = ra.x, A1 = ra.y, A2 = ra.z, A3 = ra.w;
            float B0 = rb.x, B1 = rb.y, B2 = rb.z, B3 = rb.w;
            sacc[0][0] += A0*B0; sacc[0][1] += A0*B1; sacc[0][2] += A0*B2; sacc[0][3] += A0*B3;
            sacc[1][0] += A1*B0; sacc[1][1] += A1*B1; sacc[1][2] += A1*B2; sacc[1][3] += A1*B3;
            sacc[2][0] += A2*B0; sacc[2][1] += A2*B1; sacc[2][2] += A2*B2; sacc[2][3] += A2*B3;
            sacc[3][0] += A3*B0; sacc[3][1] += A3*B1; sacc[3][2] += A3*B2; sacc[3][3] += A3*B3;
        }
        // Store S transposed: St[s][r]
        #pragma unroll
        for (int j = 0; j < 4; j++)
            #pragma unroll
            for (int i = 0; i < 4; i++)
                St[(tx*4 + j)*68 + ty*4 + i] = sacc[i][j];
        __syncthreads();

        // Row max (4 partials per row)
        {
            int r = tid & 63, part = tid >> 6;
            float pm = -INFINITY;
            #pragma unroll
            for (int s = 0; s < 16; s++)
                pm = fmaxf(pm, St[(part*16 + s)*68 + r]);
            pmax[part*64 + r] = pm;
        }
        __syncthreads();
        if (tid < 64) {
            int r = tid;
            float mt = fmaxf(fmaxf(pmax[r], pmax[64 + r]),
                             fmaxf(pmax[128 + r], pmax[192 + r]));
            float m_old = m_s[r];
            float m_new = fmaxf(m_old, mt);
            float rs = __expf(m_old - m_new);   // 0 on first tile (-inf)
            rs_s[r] = rs;
            m_s[r]  = m_new;
            l_s[r] *= rs;
        }
        __syncthreads();

        // exp in place + partial sums
        {
            int r = tid & 63, part = tid >> 6;
            float mval = m_s[r];
            float ps = 0.f;
            #pragma unroll
            for (int s = 0; s < 16; s++) {
                float p = __expf(St[(part*16 + s)*68 + r] - mval);
                St[(part*16 + s)*68 + r] = p;
                ps += p;
            }
            psum[part*64 + r] = ps;
        }
        // Rescale accumulator (rs_s was synced above)
        {
            float rs0 = rs_s[ty*4+0], rs1 = rs_s[ty*4+1];
            float rs2 = rs_s[ty*4+2], rs3 = rs_s[ty*4+3];
            #pragma unroll
            for (int j = 0; j < 8; j++) {
                acc[0][j] *= rs0; acc[1][j] *= rs1;
                acc[2][j] *= rs2; acc[3][j] *= rs3;
            }
        }
        __syncthreads();
        if (tid < 64)
            l_s[tid] += psum[tid] + psum[64 + tid] + psum[128 + tid] + psum[192 + tid];

        // O += P V : thread -> O[ty*4+i][tx*8+j]
        #pragma unroll 4
        for (int s = 0; s < 64; s++) {
            float4 rp  = *(const float4*)&St[s*68 + ty*4];
            float4 rv0 = *(const float4*)&Vs[s*128 + tx*8];
            float4 rv1 = *(const float4*)&Vs[s*128 + tx*8 + 4];
            float P0 = rp.x, P1 = rp.y, P2 = rp.z, P3 = rp.w;
            acc[0][0] += P0*rv0.x; acc[0][1] += P0*rv0.y; acc[0][2] += P0*rv0.z; acc[0][3] += P0*rv0.w;
            acc[0][4] += P0*rv1.x; acc[0][5] += P0*rv1.y; acc[0][6] += P0*rv1.z; acc[0][7] += P0*rv1.w;
            acc[1][0] += P1*rv0.x; acc[1][1] += P1*rv0.y; acc[1][2] += P1*rv0.z; acc[1][3] += P1*rv0.w;
            acc[1][4] += P1*rv1.x; acc[1][5] += P1*rv1.y; acc[1][6] += P1*rv1.z; acc[1][7] += P1*rv1.w;
            acc[2][0] += P2*rv0.x; acc[2][1] += P2*rv0.y; acc[2][2] += P2*rv0.z; acc[2][3] += P2*rv0.w;
            acc[2][4] += P2*rv1.x; acc[2][5] += P2*rv1.y; acc[2][6] += P2*rv1.z; acc[2][7] += P2*rv1.w;
            acc[3][0] += P3*rv0.x; acc[3][1] += P3*rv0.y; acc[3][2] += P3*rv0.z; acc[3][3] += P3*rv0.w;
            acc[3][4] += P3*rv1.x; acc[3][5] += P3*rv1.y; acc[3][6] += P3*rv1.z; acc[3][7] += P3*rv1.w;
        }
        __syncthreads();
    }

    // Epilogue: normalize and store
    #pragma unroll
    for (int i = 0; i < 4; i++) {
        int r = ty*4 + i;
        float invl = 1.0f / l_s[r];
        float* dst = O + (size_t)(b*T_ + q0 + r) * D_ + h*HD_ + tx*8;
        *(float4*)(dst)   = make_float4(acc[i][0]*invl, acc[i][1]*invl,
                                        acc[i][2]*invl, acc[i][3]*invl);
        *(float4*)(dst+4) = make_float4(acc[i][4]*invl, acc[i][5]*invl,
                                        acc[i][6]*invl, acc[i][7]*invl);
    }
}

// ---------------- launch -----------------------------------------------------
extern "C" void kernel_launch(void* const* d_in, const int* in_sizes, int n_in,
                              void* d_out, int out_size)
{
    const float* x  = (const float*)d_in[0];
    const float* wq = (const float*)d_in[1];
    const float* wk = (const float*)d_in[2];
    const float* wv = (const float*)d_in[3];
    const float* wo = (const float*)d_in[4];
    float* out = (float*)d_out;

    float *pQ, *pK, *pV, *pO;
    cudaGetSymbolAddress((void**)&pQ, g_Q);
    cudaGetSymbolAddress((void**)&pK, g_K);
    cudaGetSymbolAddress((void**)&pV, g_V);
    cudaGetSymbolAddress((void**)&pO, g_O);

    // Attribute persists from the first (non-captured) call; ignore errors.
    cudaFuncSetAttribute(flash_attn, cudaFuncAttributeMaxDynamicSharedMemorySize,
                         FA_SMEM_BYTES);

    dim3 thr(256);

    // QKV projections
    sgemm_nt<<<dim3(D_/128,   M_/128), thr>>>(x, wq, pQ, M_, D_,   D_);
    sgemm_nt<<<dim3(KVD_/128, M_/128), thr>>>(x, wk, pK, M_, KVD_, D_);
    sgemm_nt<<<dim3(KVD_/128, M_/128), thr>>>(x, wv, pV, M_, KVD_, D_);

    // RoPE on Q and K
    int nq = M_ * H_  * (HD_/2);
    int nk = M_ * KV_ * (HD_/2);
    rope_kernel<<<(nq + 255)/256, 256>>>(pQ, H_,  nq);
    rope_kernel<<<(nk + 255)/256, 256>>>(pK, KV_, nk);

    // Attention
    flash_attn<<<dim3(T_/64, H_, B_), thr, FA_SMEM_BYTES>>>(pQ, pK, pV, pO);

    // Output projection
    sgemm_nt<<<dim3(D_/128, M_/128), thr>>>(pO, wo, out, M_, D_, D_);
}

// round 4
// speedup vs baseline: 2.8918x; 2.8918x over previous
#include <cuda_runtime.h>
#include <cuda_fp16.h>
#include <cstdint>
#include <math.h>

#define B_  2
#define T_  2048
#define D_  2048
#define H_  16
#define KV_ 4
#define HD_ 128
#define M_  (B_*T_)    // 4096
#define KVD_ (KV_*HD_) // 512

// ---------------- scratch ----------------------------------------------------
__device__ float g_Q[M_ * D_];
__device__ float g_K[M_ * KVD_];
__device__ float g_V[M_ * KVD_];
__device__ float g_O[M_ * D_];

// ---------------- helpers -----------------------------------------------------
// Split two floats into packed fp16 hi and fp16 lo (residual) half2 words.
__device__ __forceinline__ void cvt2(float x, float y, uint32_t& h, uint32_t& l) {
    __half2 hh = __floats2half2_rn(x, y);
    float2 hf = __half22float2(hh);
    __half2 ll = __floats2half2_rn(x - hf.x, y - hf.y);
    h = *reinterpret_cast<uint32_t*>(&hh);
    l = *reinterpret_cast<uint32_t*>(&ll);
}
// D += A(16x16 row) * B(16x8 col), fp16 inputs, fp32 accum
__device__ __forceinline__ void mma_f16(float* c, const uint32_t* a, const uint32_t* b) {
    asm volatile(
        "mma.sync.aligned.m16n8k16.row.col.f32.f16.f16.f32 "
        "{%0,%1,%2,%3}, {%4,%5,%6,%7}, {%8,%9}, {%0,%1,%2,%3};"
        : "+f"(c[0]), "+f"(c[1]), "+f"(c[2]), "+f"(c[3])
        : "r"(a[0]), "r"(a[1]), "r"(a[2]), "r"(a[3]), "r"(b[0]), "r"(b[1]));
}

// ============================================================================
// fp16-split GEMM: C[m,n] = sum_k A[m,k]*W[n,k]   (3-term Markidis, fp32 acc)
// CTA 128x128x32, 256 thr (8 warps), warp tile m32 x n64, double-buffered.
// Smem rows: 16 half2-pairs + pad -> stride 20 u32 (conflict-free fragments).
// ============================================================================
#define GPU32 20
#define GT    (128*GPU32)      // u32 per tile (2560)
#define GS_BYTES (8*GT*4)      // Ah,Al,Bh,Bl x2 buffers = 81920 B

__global__ __launch_bounds__(256) void gemm_h2(
    const float* __restrict__ A, const float* __restrict__ W,
    float* __restrict__ C, int M, int N, int K)
{
    extern __shared__ uint32_t su[];
    const int tid = threadIdx.x, lane = tid & 31, w = tid >> 5;
    const int bm = blockIdx.y * 128, bn = blockIdx.x * 128;
    const int wm = (w >> 1) * 32;      // 4 m-warps
    const int wn = (w & 1) * 64;       // 2 n-warps
    const int g  = lane >> 2, t = lane & 3;
    const int lrow = tid >> 1;         // 0..127
    const int pb   = (tid & 1) * 8;    // pair base (0 or 8)

    float acc[2][8][4];
    #pragma unroll
    for (int mb = 0; mb < 2; mb++)
        #pragma unroll
        for (int nb = 0; nb < 8; nb++)
            #pragma unroll
            for (int i = 0; i < 4; i++) acc[mb][nb][i] = 0.f;

    const float* Aptr = A + (size_t)(bm + lrow) * K + pb * 2;
    const float* Wptr = W + (size_t)(bn + lrow) * K + pb * 2;

    float4 ra[4], rb[4];
    #pragma unroll
    for (int i = 0; i < 4; i++) {
        ra[i] = *(const float4*)(Aptr + i * 4);
        rb[i] = *(const float4*)(Wptr + i * 4);
    }

    const int NT = K >> 5;
    for (int kt = 0; kt < NT; kt++) {
        uint32_t* base = su + (kt & 1) * 4 * GT;
        uint32_t* Ah = base;
        uint32_t* Al = base + GT;
        uint32_t* Bh = base + 2 * GT;
        uint32_t* Bl = base + 3 * GT;

        #pragma unroll
        for (int i = 0; i < 4; i++) {
            float va[4], vb[4];
            *(float4*)va = ra[i]; *(float4*)vb = rb[i];
            uint32_t h0, l0, h1, l1;
            int off = lrow * GPU32 + pb + 2 * i;
            cvt2(va[0], va[1], h0, l0); cvt2(va[2], va[3], h1, l1);
            *(uint2*)(Ah + off) = make_uint2(h0, h1);
            *(uint2*)(Al + off) = make_uint2(l0, l1);
            cvt2(vb[0], vb[1], h0, l0); cvt2(vb[2], vb[3], h1, l1);
            *(uint2*)(Bh + off) = make_uint2(h0, h1);
            *(uint2*)(Bl + off) = make_uint2(l0, l1);
        }
        __syncthreads();

        if (kt + 1 < NT) {
            const float* An = Aptr + (kt + 1) * 32;
            const float* Wn = Wptr + (kt + 1) * 32;
            #pragma unroll
            for (int i = 0; i < 4; i++) {
                ra[i] = *(const float4*)(An + i * 4);
                rb[i] = *(const float4*)(Wn + i * 4);
            }
        }

        #pragma unroll
        for (int ks = 0; ks < 2; ks++) {
            const int kp = ks * 8 + t;
            uint32_t ah[2][4], al[2][4];
            #pragma unroll
            for (int mb = 0; mb < 2; mb++) {
                int r = wm + mb * 16 + g;
                ah[mb][0] = Ah[r*GPU32 + kp];     ah[mb][1] = Ah[(r+8)*GPU32 + kp];
                ah[mb][2] = Ah[r*GPU32 + kp + 4]; ah[mb][3] = Ah[(r+8)*GPU32 + kp + 4];
                al[mb][0] = Al[r*GPU32 + kp];     al[mb][1] = Al[(r+8)*GPU32 + kp];
                al[mb][2] = Al[r*GPU32 + kp + 4]; al[mb][3] = Al[(r+8)*GPU32 + kp + 4];
            }
            #pragma unroll
            for (int nb = 0; nb < 8; nb++) {
                int n = wn + nb * 8 + g;
                uint32_t bh[2], bl[2];
                bh[0] = Bh[n*GPU32 + kp]; bh[1] = Bh[n*GPU32 + kp + 4];
                bl[0] = Bl[n*GPU32 + kp]; bl[1] = Bl[n*GPU32 + kp + 4];
                #pragma unroll
                for (int mb = 0; mb < 2; mb++) {
                    mma_f16(acc[mb][nb], ah[mb], bh);
                    mma_f16(acc[mb][nb], ah[mb], bl);
                    mma_f16(acc[mb][nb], al[mb], bh);
                }
            }
        }
        __syncthreads();
    }

    #pragma unroll
    for (int mb = 0; mb < 2; mb++) {
        int r0 = bm + wm + mb * 16 + g;
        #pragma unroll
        for (int nb = 0; nb < 8; nb++) {
            int cc = bn + wn + nb * 8 + 2 * t;
            *(float2*)(C + (size_t)r0 * N + cc)       = make_float2(acc[mb][nb][0], acc[mb][nb][1]);
            *(float2*)(C + (size_t)(r0 + 8) * N + cc) = make_float2(acc[mb][nb][2], acc[mb][nb][3]);
        }
    }
}

// ---------------- RoPE (in-place) -------------------------------------------
__global__ void rope_kernel(float* __restrict__ X, int nheads, int total)
{
    int idx = blockIdx.x * blockDim.x + threadIdx.x;
    if (idx >= total) return;
    int j = idx & 63;
    int h = (idx >> 6) % nheads;
    int m = idx / (64 * nheads);
    int t = m & (T_ - 1);

    float inv = powf(10000.0f, -((float)(2 * j) / (float)HD_));
    float ang = (float)t * inv;
    float s, c;
    sincosf(ang, &s, &c);

    float* row = X + (size_t)m * (nheads * HD_) + h * HD_;
    float x1 = row[j], x2 = row[j + 64];
    row[j]      = x1 * c - x2 * s;
    row[j + 64] = x2 * c + x1 * s;
}

// ============================================================================
// fp16-split flash attention (3-term everywhere, fp32 softmax/stats)
// Block = (b, h, 64 q rows). 256 thr (8 warps). KV tile = 128.
// Warp grid: 2 (m) x 4 (n); warp tile m32 x n32. Row stride 68 u32.
// ============================================================================
#define AP 68
#define QH_OFF 0
#define QL_OFF (QH_OFF + 64*AP)     // 4352
#define KH_OFF (QL_OFF + 64*AP)     // 8704
#define KL_OFF (KH_OFF + 128*AP)    // 17408
#define VH_OFF (KL_OFF + 128*AP)    // 26112
#define VL_OFF (VH_OFF + 128*AP)    // 34816
#define PH_OFF (VL_OFF + 128*AP)    // 43520
#define PL_OFF (PH_OFF + 64*AP)     // 47872
#define ST_OFF (PL_OFF + 64*AP)     // 52224 (floats from here)
#define FA_SMEM_BYTES ((ST_OFF + 64*3 + 4*64*2) * 4)   // 211712 B

__global__ __launch_bounds__(256) void flash_attn_h2(
    const float* __restrict__ Q, const float* __restrict__ Kg,
    const float* __restrict__ Vg, float* __restrict__ O)
{
    extern __shared__ uint32_t su[];
    uint32_t* Qh = su + QH_OFF;  uint32_t* Ql = su + QL_OFF;
    uint32_t* Kh = su + KH_OFF;  uint32_t* Kl = su + KL_OFF;
    uint32_t* Vh = su + VH_OFF;  uint32_t* Vl = su + VL_OFF;
    uint32_t* Ph = su + PH_OFF;  uint32_t* Pl = su + PL_OFF;
    float* m_s  = (float*)(su + ST_OFF);
    float* l_s  = m_s + 64;
    float* rs_s = l_s + 64;
    float* pmax = rs_s + 64;     // [4][64]
    float* psum = pmax + 4*64;   // [4][64]

    const int tid = threadIdx.x, lane = tid & 31, w = tid >> 5;
    const int qt = blockIdx.x, h = blockIdx.y, b = blockIdx.z;
    const int gq = h >> 2;
    const int q0 = qt * 64;
    const int wm = (w & 1) * 32;    // 2 m-warps
    const int wn = (w >> 1) * 32;   // 4 n-warps
    const int g  = lane >> 2, t = lane & 3;
    const float scale = 0.08838834764831845f; // 1/sqrt(128)

    // Load Q tile (64 x 128), pre-scaled, split hi/lo
    #pragma unroll
    for (int it = 0; it < 8; it++) {
        int lin = tid + it * 256;
        int c4 = lin & 31, r = lin >> 5;
        float4 v = *(const float4*)(Q + (size_t)(b*T_ + q0 + r) * D_ + h*HD_ + c4*4);
        uint32_t h0, l0, h1, l1;
        cvt2(v.x*scale, v.y*scale, h0, l0);
        cvt2(v.z*scale, v.w*scale, h1, l1);
        *(uint2*)(Qh + r*AP + c4*2) = make_uint2(h0, h1);
        *(uint2*)(Ql + r*AP + c4*2) = make_uint2(l0, l1);
    }
    if (tid < 64) { m_s[tid] = -INFINITY; l_s[tid] = 0.f; }

    float acc[2][4][4];
    #pragma unroll
    for (int mb = 0; mb < 2; mb++)
        #pragma unroll
        for (int nb = 0; nb < 4; nb++)
            #pragma unroll
            for (int i = 0; i < 4; i++) acc[mb][nb][i] = 0.f;
    __syncthreads();

    for (int s0 = 0; s0 < T_; s0 += 128) {
        // K tile (128 x 128) K-major, split
        #pragma unroll
        for (int it = 0; it < 16; it++) {
            int lin = tid + it * 256;
            int c4 = lin & 31, r = lin >> 5;
            float4 v = *(const float4*)(Kg + (size_t)(b*T_ + s0 + r) * KVD_ + gq*HD_ + c4*4);
            uint32_t h0, l0, h1, l1;
            cvt2(v.x, v.y, h0, l0);
            cvt2(v.z, v.w, h1, l1);
            *(uint2*)(Kh + r*AP + c4*2) = make_uint2(h0, h1);
            *(uint2*)(Kl + r*AP + c4*2) = make_uint2(l0, l1);
        }
        // V tile transposed: Vt[d][s-pairs], split
        #pragma unroll
        for (int it = 0; it < 4; it++) {
            int lin = tid + it * 256;
            int c4 = lin & 31, rb = lin >> 5;   // rb: group of 4 s-rows
            float v0[4], v1[4], v2[4], v3[4];
            *(float4*)v0 = *(const float4*)(Vg + (size_t)(b*T_ + s0 + rb*4 + 0) * KVD_ + gq*HD_ + c4*4);
            *(float4*)v1 = *(const float4*)(Vg + (size_t)(b*T_ + s0 + rb*4 + 1) * KVD_ + gq*HD_ + c4*4);
            *(float4*)v2 = *(const float4*)(Vg + (size_t)(b*T_ + s0 + rb*4 + 2) * KVD_ + gq*HD_ + c4*4);
            *(float4*)v3 = *(const float4*)(Vg + (size_t)(b*T_ + s0 + rb*4 + 3) * KVD_ + gq*HD_ + c4*4);
            #pragma unroll
            for (int dj = 0; dj < 4; dj++) {
                int d = c4 * 4 + dj;
                uint32_t h0, l0, h1, l1;
                cvt2(v0[dj], v1[dj], h0, l0);
                cvt2(v2[dj], v3[dj], h1, l1);
                *(uint2*)(Vh + d*AP + rb*2) = make_uint2(h0, h1);
                *(uint2*)(Vl + d*AP + rb*2) = make_uint2(l0, l1);
            }
        }
        __syncthreads();

        // ---- S = Q K^T (64 x 128) ----
        float sfr[2][4][4];
        #pragma unroll
        for (int mb = 0; mb < 2; mb++)
            #pragma unroll
            for (int nb = 0; nb < 4; nb++)
                #pragma unroll
                for (int i = 0; i < 4; i++) sfr[mb][nb][i] = 0.f;

        #pragma unroll
        for (int k16 = 0; k16 < 8; k16++) {
            const int kp = k16 * 8 + t;
            uint32_t ah[2][4], al[2][4];
            #pragma unroll
            for (int mb = 0; mb < 2; mb++) {
                int r = wm + mb * 16 + g;
                ah[mb][0] = Qh[r*AP + kp];     ah[mb][1] = Qh[(r+8)*AP + kp];
                ah[mb][2] = Qh[r*AP + kp + 4]; ah[mb][3] = Qh[(r+8)*AP + kp + 4];
                al[mb][0] = Ql[r*AP + kp];     al[mb][1] = Ql[(r+8)*AP + kp];
                al[mb][2] = Ql[r*AP + kp + 4]; al[mb][3] = Ql[(r+8)*AP + kp + 4];
            }
            #pragma unroll
            for (int nb = 0; nb < 4; nb++) {
                int n = wn + nb * 8 + g;
                uint32_t bh[2], bl[2];
                bh[0] = Kh[n*AP + kp]; bh[1] = Kh[n*AP + kp + 4];
                bl[0] = Kl[n*AP + kp]; bl[1] = Kl[n*AP + kp + 4];
                #pragma unroll
                for (int mb = 0; mb < 2; mb++) {
                    mma_f16(sfr[mb][nb], ah[mb], bh);
                    mma_f16(sfr[mb][nb], ah[mb], bl);
                    mma_f16(sfr[mb][nb], al[mb], bh);
                }
            }
        }

        // ---- row max ----
        #pragma unroll
        for (int mb = 0; mb < 2; mb++) {
            float m0 = -INFINITY, m1 = -INFINITY;
            #pragma unroll
            for (int nb = 0; nb < 4; nb++) {
                m0 = fmaxf(m0, fmaxf(sfr[mb][nb][0], sfr[mb][nb][1]));
                m1 = fmaxf(m1, fmaxf(sfr[mb][nb][2], sfr[mb][nb][3]));
            }
            m0 = fmaxf(m0, __shfl_xor_sync(0xffffffffu, m0, 1));
            m0 = fmaxf(m0, __shfl_xor_sync(0xffffffffu, m0, 2));
            m1 = fmaxf(m1, __shfl_xor_sync(0xffffffffu, m1, 1));
            m1 = fmaxf(m1, __shfl_xor_sync(0xffffffffu, m1, 2));
            if (t == 0) {
                pmax[(w>>1)*64 + wm + mb*16 + g    ] = m0;
                pmax[(w>>1)*64 + wm + mb*16 + g + 8] = m1;
            }
        }
        __syncthreads();
        if (tid < 64) {
            int r = tid;
            float mt = fmaxf(fmaxf(pmax[r], pmax[64+r]), fmaxf(pmax[128+r], pmax[192+r]));
            float m_old = m_s[r];
            float m_new = fmaxf(m_old, mt);
            float rs = __expf(m_old - m_new);
            rs_s[r] = rs; m_s[r] = m_new; l_s[r] *= rs;
        }
        __syncthreads();

        // ---- exp, P->smem split, partial sums; rescale acc ----
        float ps[2][2] = {{0.f,0.f},{0.f,0.f}};
        #pragma unroll
        for (int mb = 0; mb < 2; mb++) {
            int row0 = wm + mb*16 + g;
            float m0 = m_s[row0], m1 = m_s[row0 + 8];
            #pragma unroll
            for (int nb = 0; nb < 4; nb++) {
                int pp = (wn >> 1) + nb*4 + t;   // pair column
                float p0 = __expf(sfr[mb][nb][0] - m0);
                float p1 = __expf(sfr[mb][nb][1] - m0);
                float p2 = __expf(sfr[mb][nb][2] - m1);
                float p3 = __expf(sfr[mb][nb][3] - m1);
                ps[mb][0] += p0 + p1;
                ps[mb][1] += p2 + p3;
                uint32_t hh, ll;
                cvt2(p0, p1, hh, ll);
                Ph[row0*AP + pp] = hh; Pl[row0*AP + pp] = ll;
                cvt2(p2, p3, hh, ll);
                Ph[(row0+8)*AP + pp] = hh; Pl[(row0+8)*AP + pp] = ll;
            }
            ps[mb][0] += __shfl_xor_sync(0xffffffffu, ps[mb][0], 1);
            ps[mb][0] += __shfl_xor_sync(0xffffffffu, ps[mb][0], 2);
            ps[mb][1] += __shfl_xor_sync(0xffffffffu, ps[mb][1], 1);
            ps[mb][1] += __shfl_xor_sync(0xffffffffu, ps[mb][1], 2);
            if (t == 0) {
                psum[(w>>1)*64 + wm + mb*16 + g    ] = ps[mb][0];
                psum[(w>>1)*64 + wm + mb*16 + g + 8] = ps[mb][1];
            }
        }
        // rescale accumulators
        #pragma unroll
        for (int mb = 0; mb < 2; mb++) {
            int row0 = wm + mb*16 + g;
            float r0 = rs_s[row0], r1 = rs_s[row0 + 8];
            #pragma unroll
            for (int nb = 0; nb < 4; nb++) {
                acc[mb][nb][0] *= r0; acc[mb][nb][1] *= r0;
                acc[mb][nb][2] *= r1; acc[mb][nb][3] *= r1;
            }
        }
        __syncthreads();
        if (tid < 64)
            l_s[tid] += psum[tid] + psum[64+tid] + psum[128+tid] + psum[192+tid];

        // ---- O += P V (64 x 128), k = s ----
        #pragma unroll
        for (int k16 = 0; k16 < 8; k16++) {
            const int kp = k16 * 8 + t;
            uint32_t ah[2][4], al[2][4];
            #pragma unroll
            for (int mb = 0; mb < 2; mb++) {
                int r = wm + mb * 16 + g;
                ah[mb][0] = Ph[r*AP + kp];     ah[mb][1] = Ph[(r+8)*AP + kp];
                ah[mb][2] = Ph[r*AP + kp + 4]; ah[mb][3] = Ph[(r+8)*AP + kp + 4];
                al[mb][0] = Pl[r*AP + kp];     al[mb][1] = Pl[(r+8)*AP + kp];
                al[mb][2] = Pl[r*AP + kp + 4]; al[mb][3] = Pl[(r+8)*AP + kp + 4];
            }
            #pragma unroll
            for (int nb = 0; nb < 4; nb++) {
                int n = wn + nb * 8 + g;        // d index
                uint32_t bh[2], bl[2];
                bh[0] = Vh[n*AP + kp]; bh[1] = Vh[n*AP + kp + 4];
                bl[0] = Vl[n*AP + kp]; bl[1] = Vl[n*AP + kp + 4];
                #pragma unroll
                for (int mb = 0; mb < 2; mb++) {
                    mma_f16(acc[mb][nb], ah[mb], bh);
                    mma_f16(acc[mb][nb], ah[mb], bl);
                    mma_f16(acc[mb][nb], al[mb], bh);
                }
            }
        }
        __syncthreads();
    }

    // ---- epilogue ----
    #pragma unroll
    for (int mb = 0; mb < 2; mb++) {
        int row0 = wm + mb*16 + g;
        float inv0 = 1.0f / l_s[row0];
        float inv1 = 1.0f / l_s[row0 + 8];
        #pragma unroll
        for (int nb = 0; nb < 4; nb++) {
            int col = h*HD_ + wn + nb*8 + 2*t;
            float* d0 = O + (size_t)(b*T_ + q0 + row0) * D_ + col;
            float* d1 = O + (size_t)(b*T_ + q0 + row0 + 8) * D_ + col;
            *(float2*)d0 = make_float2(acc[mb][nb][0]*inv0, acc[mb][nb][1]*inv0);
            *(float2*)d1 = make_float2(acc[mb][nb][2]*inv1, acc[mb][nb][3]*inv1);
        }
    }
}

// ---------------- launch ------------------------------------------------------
extern "C" void kernel_launch(void* const* d_in, const int* in_sizes, int n_in,
                              void* d_out, int out_size)
{
    const float* x  = (const float*)d_in[0];
    const float* wq = (const float*)d_in[1];
    const float* wk = (const float*)d_in[2];
    const float* wv = (const float*)d_in[3];
    const float* wo = (const float*)d_in[4];
    float* out = (float*)d_out;

    float *pQ, *pK, *pV, *pO;
    cudaGetSymbolAddress((void**)&pQ, g_Q);
    cudaGetSymbolAddress((void**)&pK, g_K);
    cudaGetSymbolAddress((void**)&pV, g_V);
    cudaGetSymbolAddress((void**)&pO, g_O);

    cudaFuncSetAttribute(gemm_h2, cudaFuncAttributeMaxDynamicSharedMemorySize, GS_BYTES);
    cudaFuncSetAttribute(flash_attn_h2, cudaFuncAttributeMaxDynamicSharedMemorySize, FA_SMEM_BYTES);

    // QKV projections
    gemm_h2<<<dim3(D_/128,   M_/128), 256, GS_BYTES>>>(x, wq, pQ, M_, D_,   D_);
    gemm_h2<<<dim3(KVD_/128, M_/128), 256, GS_BYTES>>>(x, wk, pK, M_, KVD_, D_);
    gemm_h2<<<dim3(KVD_/128, M_/128), 256, GS_BYTES>>>(x, wv, pV, M_, KVD_, D_);

    // RoPE
    int nq = M_ * H_  * (HD_/2);
    int nk = M_ * KV_ * (HD_/2);
    rope_kernel<<<(nq + 255)/256, 256>>>(pQ, H_,  nq);
    rope_kernel<<<(nk + 255)/256, 256>>>(pK, KV_, nk);

    // Attention
    flash_attn_h2<<<dim3(T_/64, H_, B_), 256, FA_SMEM_BYTES>>>(pQ, pK, pV, pO);

    // Output projection
    gemm_h2<<<dim3(D_/128, M_/128), 256, GS_BYTES>>>(pO, wo, out, M_, D_, D_);
}

// round 6
// speedup vs baseline: 3.7686x; 1.3032x over previous
#include <cuda_runtime.h>
#include <cuda_fp16.h>
#include <cstdint>
#include <math.h>

#define B_  2
#define T_  2048
#define D_  2048
#define H_  16
#define KV_ 4
#define HD_ 128
#define M_  (B_*T_)    // 4096
#define KVD_ (KV_*HD_) // 512

// ---------------- scratch ----------------------------------------------------
__device__ float  g_Qf[M_ * D_];
__device__ float  g_Kf[M_ * KVD_];
__device__ float  g_Vf[M_ * KVD_];
__device__ __half g_Xh[M_*D_],    g_Xl[M_*D_];
__device__ __half g_Wqh[D_*D_],   g_Wql[D_*D_];
__device__ __half g_Wkh[KVD_*D_], g_Wkl[KVD_*D_];
__device__ __half g_Wvh[KVD_*D_], g_Wvl[KVD_*D_];
__device__ __half g_Woh[D_*D_],   g_Wol[D_*D_];
__device__ __half g_Qh[M_*D_],    g_Ql[M_*D_];
__device__ __half g_Kh2[M_*KVD_], g_Kl2[M_*KVD_];
__device__ __half g_Vth[M_*KVD_], g_Vtl[M_*KVD_];  // [(b*KV+g)*128+d][T]
__device__ __half g_Oh[M_*D_],    g_Ol[M_*D_];

// ---------------- helpers -----------------------------------------------------
__device__ __forceinline__ void cvt2(float x, float y, uint32_t& h, uint32_t& l) {
    __half2 hh = __floats2half2_rn(x, y);
    float2 hf = __half22float2(hh);
    __half2 ll = __floats2half2_rn(x - hf.x, y - hf.y);
    h = *reinterpret_cast<uint32_t*>(&hh);
    l = *reinterpret_cast<uint32_t*>(&ll);
}
__device__ __forceinline__ void mma_f16(float* c, const uint32_t* a, const uint32_t* b) {
    asm volatile(
        "mma.sync.aligned.m16n8k16.row.col.f32.f16.f16.f32 "
        "{%0,%1,%2,%3}, {%4,%5,%6,%7}, {%8,%9}, {%0,%1,%2,%3};"
        : "+f"(c[0]), "+f"(c[1]), "+f"(c[2]), "+f"(c[3])
        : "r"(a[0]), "r"(a[1]), "r"(a[2]), "r"(a[3]), "r"(b[0]), "r"(b[1]));
}
__device__ __forceinline__ uint32_t s2u(const void* p) {
    uint32_t a;
    asm("{ .reg .u64 t; cvta.to.shared.u64 t, %1; cvt.u32.u64 %0, t; }" : "=r"(a) : "l"(p));
    return a;
}
#define CP16(dst, src) asm volatile("cp.async.cg.shared.global [%0], [%1], 16;" :: "r"(dst), "l"(src))
#define CPC   asm volatile("cp.async.commit_group;" ::: "memory")
#define CPW0  asm volatile("cp.async.wait_group 0;" ::: "memory")
#define CPW1  asm volatile("cp.async.wait_group 1;" ::: "memory")

// ---------------- pre-split kernels -------------------------------------------
__global__ void split_f32(const float* __restrict__ X,
                          __half* __restrict__ Xh, __half* __restrict__ Xl, int n4)
{
    int i = blockIdx.x * blockDim.x + threadIdx.x;
    if (i >= n4) return;
    float4 v = *(const float4*)(X + (size_t)i * 4);
    uint32_t h0, l0, h1, l1;
    cvt2(v.x, v.y, h0, l0);
    cvt2(v.z, v.w, h1, l1);
    *(uint2*)(Xh + (size_t)i * 4) = make_uint2(h0, h1);
    *(uint2*)(Xl + (size_t)i * 4) = make_uint2(l0, l1);
}

// RoPE + split: reads f32 [m][nheads*128], rotates, scales, writes hi/lo fp16.
// Pair index j in 0..63; this thread handles j = 2*j2 and 2*j2+1.
// inv_freq[j] = 10000^(-2j/128)  (matches reference arange(0,128,2)/128)
__global__ void rope_split(const float* __restrict__ X,
                           __half* __restrict__ Xh, __half* __restrict__ Xl,
                           int nheads, float scale, int total)
{
    int idx = blockIdx.x * blockDim.x + threadIdx.x;
    if (idx >= total) return;
    int j2 = idx & 31;
    int hh = (idx >> 5) % nheads;
    int m  = idx / (32 * nheads);
    int t  = m & (T_ - 1);

    size_t ro = (size_t)m * (nheads * HD_) + hh * HD_;
    float2 a  = *(const float2*)(X + ro + j2*2);
    float2 bq = *(const float2*)(X + ro + 64 + j2*2);

    float inv0 = powf(10000.0f, -((float)(2 * (2*j2))     / 128.0f));
    float inv1 = powf(10000.0f, -((float)(2 * (2*j2 + 1)) / 128.0f));
    float s0, c0, s1, c1;
    sincosf((float)t * inv0, &s0, &c0);
    sincosf((float)t * inv1, &s1, &c1);

    float o0 = (a.x * c0 - bq.x * s0) * scale;
    float o1 = (a.y * c1 - bq.y * s1) * scale;
    float o2 = (bq.x * c0 + a.x * s0) * scale;
    float o3 = (bq.y * c1 + a.y * s1) * scale;

    uint32_t ph, pl;
    cvt2(o0, o1, ph, pl);
    *(uint32_t*)(Xh + ro + j2*2) = ph;
    *(uint32_t*)(Xl + ro + j2*2) = pl;
    cvt2(o2, o3, ph, pl);
    *(uint32_t*)(Xh + ro + 64 + j2*2) = ph;
    *(uint32_t*)(Xl + ro + 64 + j2*2) = pl;
}

// V transpose + split: [b*T+t][g*128+d] f32 -> [(b*KV+g)*128+d][t] fp16 hi/lo
__global__ void vtrans_split(const float* __restrict__ V,
                             __half* __restrict__ Vh, __half* __restrict__ Vl)
{
    __shared__ float tile[32][33];
    int bx = blockIdx.x, by = blockIdx.y, b = blockIdx.z;
    int tx = threadIdx.x, ty = threadIdx.y;
    #pragma unroll
    for (int i = 0; i < 4; i++) {
        int tt = bx*32 + ty + i*8;
        int dd = by*32 + tx;
        tile[ty + i*8][tx] = V[(size_t)(b*T_ + tt) * KVD_ + dd];
    }
    __syncthreads();
    #pragma unroll
    for (int i = 0; i < 4; i++) {
        int dd = by*32 + ty + i*8;
        int tt = bx*32 + tx;
        float v = tile[tx][ty + i*8];
        __half hv = __float2half_rn(v);
        __half lv = __float2half_rn(v - __half2float(hv));
        size_t o = (size_t)(b*KVD_ + dd) * T_ + tt;
        Vh[o] = hv; Vl[o] = lv;
    }
}

// ============================================================================
// fp16-split GEMM (pre-split inputs): C[m,n] = sum_k A[m,k]*W[n,k]
// CTA 128x128x32, 256 thr, warp tile m32 x n64, cp.async double-buffered.
// ============================================================================
#define GS_BYTES (2*4*128*80)     // 81920

__global__ __launch_bounds__(256) void gemm_h3(
    const __half* __restrict__ Ah_g, const __half* __restrict__ Al_g,
    const __half* __restrict__ Bh_g, const __half* __restrict__ Bl_g,
    float* __restrict__ C, int M, int N, int K)
{
    extern __shared__ uint32_t su[];
    const uint32_t sb = s2u(su);
    const int tid = threadIdx.x, lane = tid & 31, w = tid >> 5;
    const int bm = blockIdx.y * 128, bn = blockIdx.x * 128;
    const int wm = (w >> 1) * 32;
    const int wn = (w & 1) * 64;
    const int g = lane >> 2, t = lane & 3;

    const int matid = tid >> 6;
    const __half* gp = (matid == 0) ? Ah_g : (matid == 1) ? Al_g
                     : (matid == 2) ? Bh_g : Bl_g;
    const int rowb = (matid < 2) ? bm : bn;
    const int t64 = tid & 63;
    const int rb0 = t64 >> 2, cc = t64 & 3;
    const uint32_t dstb = sb + matid*10240 + rb0*80 + cc*16;
    const __half* srcb = gp + (size_t)(rowb + rb0) * K + cc * 8;

    float acc[2][8][4];
    #pragma unroll
    for (int mb = 0; mb < 2; mb++)
        #pragma unroll
        for (int nb = 0; nb < 8; nb++)
            #pragma unroll
            for (int i = 0; i < 4; i++) acc[mb][nb][i] = 0.f;

    {
        const __half* s = srcb;
        #pragma unroll
        for (int i = 0; i < 8; i++)
            CP16(dstb + i*1280, s + (size_t)(16*i) * K);
    }
    CPC;

    const int NT = K >> 5;
    for (int kt = 0; kt < NT; kt++) {
        const int stg = kt & 1;
        CPW0;
        __syncthreads();
        if (kt + 1 < NT) {
            const __half* s = srcb + (kt + 1) * 32;
            const uint32_t d2 = dstb + (stg ^ 1) * 40960;
            #pragma unroll
            for (int i = 0; i < 8; i++)
                CP16(d2 + i*1280, s + (size_t)(16*i) * K);
        }
        CPC;

        uint32_t* Ahs = su + stg * 10240;
        uint32_t* Als = Ahs + 2560;
        uint32_t* Bhs = Ahs + 5120;
        uint32_t* Bls = Ahs + 7680;

        #pragma unroll
        for (int ks = 0; ks < 2; ks++) {
            const int kp = ks * 8 + t;
            uint32_t ah[2][4], al[2][4];
            #pragma unroll
            for (int mb = 0; mb < 2; mb++) {
                int r = wm + mb * 16 + g;
                ah[mb][0] = Ahs[r*20 + kp];     ah[mb][1] = Ahs[(r+8)*20 + kp];
                ah[mb][2] = Ahs[r*20 + kp + 4]; ah[mb][3] = Ahs[(r+8)*20 + kp + 4];
                al[mb][0] = Als[r*20 + kp];     al[mb][1] = Als[(r+8)*20 + kp];
                al[mb][2] = Als[r*20 + kp + 4]; al[mb][3] = Als[(r+8)*20 + kp + 4];
            }
            #pragma unroll
            for (int nb = 0; nb < 8; nb++) {
                int n = wn + nb * 8 + g;
                uint32_t bh2[2], bl2[2];
                bh2[0] = Bhs[n*20 + kp]; bh2[1] = Bhs[n*20 + kp + 4];
                bl2[0] = Bls[n*20 + kp]; bl2[1] = Bls[n*20 + kp + 4];
                #pragma unroll
                for (int mb = 0; mb < 2; mb++) {
                    mma_f16(acc[mb][nb], ah[mb], bh2);
                    mma_f16(acc[mb][nb], ah[mb], bl2);
                    mma_f16(acc[mb][nb], al[mb], bh2);
                }
            }
        }
    }

    #pragma unroll
    for (int mb = 0; mb < 2; mb++) {
        int r0 = bm + wm + mb * 16 + g;
        #pragma unroll
        for (int nb = 0; nb < 8; nb++) {
            int ccn = bn + wn + nb * 8 + 2 * t;
            *(float2*)(C + (size_t)r0 * N + ccn)       = make_float2(acc[mb][nb][0], acc[mb][nb][1]);
            *(float2*)(C + (size_t)(r0 + 8) * N + ccn) = make_float2(acc[mb][nb][2], acc[mb][nb][3]);
        }
    }
}

// ============================================================================
// fp16-split flash attention, pre-split inputs, cp.async pipelined K/V
// ============================================================================
#define AP 68
#define QH_OFF 0
#define QL_OFF (QH_OFF + 64*AP)
#define KH_OFF (QL_OFF + 64*AP)
#define KL_OFF (KH_OFF + 128*AP)
#define VH_OFF (KL_OFF + 128*AP)
#define VL_OFF (VH_OFF + 128*AP)
#define PH_OFF (VL_OFF + 128*AP)
#define PL_OFF (PH_OFF + 64*AP)
#define ST_OFF (PL_OFF + 64*AP)
#define FA_SMEM_BYTES ((ST_OFF + 64*3 + 4*64*2) * 4)   // 211712 B

__global__ __launch_bounds__(256) void flash_attn_h3(
    const __half* __restrict__ Qh_g, const __half* __restrict__ Ql_g,
    const __half* __restrict__ Kh_g, const __half* __restrict__ Kl_g,
    const __half* __restrict__ Vh_g, const __half* __restrict__ Vl_g,
    __half* __restrict__ Oh_g, __half* __restrict__ Ol_g)
{
    extern __shared__ uint32_t su[];
    const uint32_t sb = s2u(su);
    uint32_t* Ph = su + PH_OFF;
    uint32_t* Pl = su + PL_OFF;
    float* m_s  = (float*)(su + ST_OFF);
    float* l_s  = m_s + 64;
    float* rs_s = l_s + 64;
    float* pmax = rs_s + 64;
    float* psum = pmax + 4*64;

    const int tid = threadIdx.x, lane = tid & 31, w = tid >> 5;
    const int qt = blockIdx.x, h = blockIdx.y, b = blockIdx.z;
    const int gq = h >> 2;
    const int q0 = qt * 64;
    const int wm = (w & 1) * 32;
    const int wn = (w >> 1) * 32;
    const int g = lane >> 2, t = lane & 3;

    const int vm = tid >> 7;
    const int t128 = tid & 127;
    const int qr = t128 >> 4, qc = t128 & 15;

    auto issueK = [&](int s0k) {
        const __half* src = (vm ? Kl_g : Kh_g) + (size_t)(b*T_ + s0k + qr) * KVD_ + gq*HD_ + qc*8;
        uint32_t dst = sb + (uint32_t)(KH_OFF + vm*(128*AP))*4 + qr*272 + qc*16;
        #pragma unroll
        for (int i = 0; i < 16; i++)
            CP16(dst + i*8*272, src + (size_t)(8*i) * KVD_);
    };
    auto issueV = [&](int s0v) {
        const __half* src = (vm ? Vl_g : Vh_g) + ((size_t)(b*KV_ + gq)*HD_ + qr) * T_ + s0v + qc*8;
        uint32_t dst = sb + (uint32_t)(VH_OFF + vm*(128*AP))*4 + qr*272 + qc*16;
        #pragma unroll
        for (int i = 0; i < 16; i++)
            CP16(dst + i*8*272, src + (size_t)(8*i) * T_);
    };

    {
        const __half* src = (vm ? Ql_g : Qh_g) + (size_t)(b*T_ + q0 + qr) * D_ + h*HD_ + qc*8;
        uint32_t dst = sb + (uint32_t)(QH_OFF + vm*(64*AP))*4 + qr*272 + qc*16;
        #pragma unroll
        for (int i = 0; i < 8; i++)
            CP16(dst + i*8*272, src + (size_t)(8*i) * D_);
        issueK(0);
    }
    CPC;
    issueV(0);
    CPC;

    if (tid < 64) { m_s[tid] = -INFINITY; l_s[tid] = 0.f; }

    float acc[2][4][4];
    #pragma unroll
    for (int mb = 0; mb < 2; mb++)
        #pragma unroll
        for (int nb = 0; nb < 4; nb++)
            #pragma unroll
            for (int i = 0; i < 4; i++) acc[mb][nb][i] = 0.f;

    uint32_t* Qhs = su + QH_OFF;  uint32_t* Qls = su + QL_OFF;
    uint32_t* Khs = su + KH_OFF;  uint32_t* Kls = su + KL_OFF;
    uint32_t* Vhs = su + VH_OFF;  uint32_t* Vls = su + VL_OFF;

    for (int it = 0; it < 16; it++) {
        CPW1;
        __syncthreads();

        // ---- S = Q K^T ----
        float sfr[2][4][4];
        #pragma unroll
        for (int mb = 0; mb < 2; mb++)
            #pragma unroll
            for (int nb = 0; nb < 4; nb++)
                #pragma unroll
                for (int i = 0; i < 4; i++) sfr[mb][nb][i] = 0.f;

        #pragma unroll
        for (int k16 = 0; k16 < 8; k16++) {
            const int kp = k16 * 8 + t;
            uint32_t ah[2][4], al[2][4];
            #pragma unroll
            for (int mb = 0; mb < 2; mb++) {
                int r = wm + mb * 16 + g;
                ah[mb][0] = Qhs[r*AP + kp];     ah[mb][1] = Qhs[(r+8)*AP + kp];
                ah[mb][2] = Qhs[r*AP + kp + 4]; ah[mb][3] = Qhs[(r+8)*AP + kp + 4];
                al[mb][0] = Qls[r*AP + kp];     al[mb][1] = Qls[(r+8)*AP + kp];
                al[mb][2] = Qls[r*AP + kp + 4]; al[mb][3] = Qls[(r+8)*AP + kp + 4];
            }
            #pragma unroll
            for (int nb = 0; nb < 4; nb++) {
                int n = wn + nb * 8 + g;
                uint32_t bh2[2], bl2[2];
                bh2[0] = Khs[n*AP + kp]; bh2[1] = Khs[n*AP + kp + 4];
                bl2[0] = Kls[n*AP + kp]; bl2[1] = Kls[n*AP + kp + 4];
                #pragma unroll
                for (int mb = 0; mb < 2; mb++) {
                    mma_f16(sfr[mb][nb], ah[mb], bh2);
                    mma_f16(sfr[mb][nb], ah[mb], bl2);
                    mma_f16(sfr[mb][nb], al[mb], bh2);
                }
            }
        }

        // ---- row max ----
        #pragma unroll
        for (int mb = 0; mb < 2; mb++) {
            float m0 = -INFINITY, m1 = -INFINITY;
            #pragma unroll
            for (int nb = 0; nb < 4; nb++) {
                m0 = fmaxf(m0, fmaxf(sfr[mb][nb][0], sfr[mb][nb][1]));
                m1 = fmaxf(m1, fmaxf(sfr[mb][nb][2], sfr[mb][nb][3]));
            }
            m0 = fmaxf(m0, __shfl_xor_sync(0xffffffffu, m0, 1));
            m0 = fmaxf(m0, __shfl_xor_sync(0xffffffffu, m0, 2));
            m1 = fmaxf(m1, __shfl_xor_sync(0xffffffffu, m1, 1));
            m1 = fmaxf(m1, __shfl_xor_sync(0xffffffffu, m1, 2));
            if (t == 0) {
                pmax[(w>>1)*64 + wm + mb*16 + g    ] = m0;
                pmax[(w>>1)*64 + wm + mb*16 + g + 8] = m1;
            }
        }
        __syncthreads();

        if (it + 1 < 16) issueK((it + 1) * 128);
        CPC;

        if (tid < 64) {
            int r = tid;
            float mt = fmaxf(fmaxf(pmax[r], pmax[64+r]), fmaxf(pmax[128+r], pmax[192+r]));
            float m_old = m_s[r];
            float m_new = fmaxf(m_old, mt);
            float rs = __expf(m_old - m_new);
            rs_s[r] = rs; m_s[r] = m_new; l_s[r] *= rs;
        }
        __syncthreads();

        // ---- exp, P->smem split, partial sums; rescale acc ----
        float ps[2][2] = {{0.f,0.f},{0.f,0.f}};
        #pragma unroll
        for (int mb = 0; mb < 2; mb++) {
            int row0 = wm + mb*16 + g;
            float m0 = m_s[row0], m1 = m_s[row0 + 8];
            #pragma unroll
            for (int nb = 0; nb < 4; nb++) {
                int pp = (wn >> 1) + nb*4 + t;
                float p0 = __expf(sfr[mb][nb][0] - m0);
                float p1 = __expf(sfr[mb][nb][1] - m0);
                float p2 = __expf(sfr[mb][nb][2] - m1);
                float p3 = __expf(sfr[mb][nb][3] - m1);
                ps[mb][0] += p0 + p1;
                ps[mb][1] += p2 + p3;
                uint32_t hh, ll;
                cvt2(p0, p1, hh, ll);
                Ph[row0*AP + pp] = hh; Pl[row0*AP + pp] = ll;
                cvt2(p2, p3, hh, ll);
                Ph[(row0+8)*AP + pp] = hh; Pl[(row0+8)*AP + pp] = ll;
            }
            ps[mb][0] += __shfl_xor_sync(0xffffffffu, ps[mb][0], 1);
            ps[mb][0] += __shfl_xor_sync(0xffffffffu, ps[mb][0], 2);
            ps[mb][1] += __shfl_xor_sync(0xffffffffu, ps[mb][1], 1);
            ps[mb][1] += __shfl_xor_sync(0xffffffffu, ps[mb][1], 2);
            if (t == 0) {
                psum[(w>>1)*64 + wm + mb*16 + g    ] = ps[mb][0];
                psum[(w>>1)*64 + wm + mb*16 + g + 8] = ps[mb][1];
            }
        }
        #pragma unroll
        for (int mb = 0; mb < 2; mb++) {
            int row0 = wm + mb*16 + g;
            float r0 = rs_s[row0], r1 = rs_s[row0 + 8];
            #pragma unroll
            for (int nb = 0; nb < 4; nb++) {
                acc[mb][nb][0] *= r0; acc[mb][nb][1] *= r0;
                acc[mb][nb][2] *= r1; acc[mb][nb][3] *= r1;
            }
        }
        if (it < 15) { CPW1; } else { CPW0; }
        __syncthreads();
        if (tid < 64)
            l_s[tid] += psum[tid] + psum[64+tid] + psum[128+tid] + psum[192+tid];

        // ---- O += P V ----
        #pragma unroll
        for (int k16 = 0; k16 < 8; k16++) {
            const int kp = k16 * 8 + t;
            uint32_t ah[2][4], al[2][4];
            #pragma unroll
            for (int mb = 0; mb < 2; mb++) {
                int r = wm + mb * 16 + g;
                ah[mb][0] = Ph[r*AP + kp];     ah[mb][1] = Ph[(r+8)*AP + kp];
                ah[mb][2] = Ph[r*AP + kp + 4]; ah[mb][3] = Ph[(r+8)*AP + kp + 4];
                al[mb][0] = Pl[r*AP + kp];     al[mb][1] = Pl[(r+8)*AP + kp];
                al[mb][2] = Pl[r*AP + kp + 4]; al[mb][3] = Pl[(r+8)*AP + kp + 4];
            }
            #pragma unroll
            for (int nb = 0; nb < 4; nb++) {
                int n = wn + nb * 8 + g;
                uint32_t bh2[2], bl2[2];
                bh2[0] = Vhs[n*AP + kp]; bh2[1] = Vhs[n*AP + kp + 4];
                bl2[0] = Vls[n*AP + kp]; bl2[1] = Vls[n*AP + kp + 4];
                #pragma unroll
                for (int mb = 0; mb < 2; mb++) {
                    mma_f16(acc[mb][nb], ah[mb], bh2);
                    mma_f16(acc[mb][nb], ah[mb], bl2);
                    mma_f16(acc[mb][nb], al[mb], bh2);
                }
            }
        }
        __syncthreads();

        if (it + 1 < 16) issueV((it + 1) * 128);
        CPC;
    }

    // ---- epilogue ----
    #pragma unroll
    for (int mb = 0; mb < 2; mb++) {
        int row0 = wm + mb*16 + g;
        float inv0 = 1.0f / l_s[row0];
        float inv1 = 1.0f / l_s[row0 + 8];
        #pragma unroll
        for (int nb = 0; nb < 4; nb++) {
            int col = h*HD_ + wn + nb*8 + 2*t;
            size_t o0 = (size_t)(b*T_ + q0 + row0) * D_ + col;
            size_t o1 = (size_t)(b*T_ + q0 + row0 + 8) * D_ + col;
            uint32_t hh, ll;
            cvt2(acc[mb][nb][0]*inv0, acc[mb][nb][1]*inv0, hh, ll);
            *(uint32_t*)(Oh_g + o0) = hh; *(uint32_t*)(Ol_g + o0) = ll;
            cvt2(acc[mb][nb][2]*inv1, acc[mb][nb][3]*inv1, hh, ll);
            *(uint32_t*)(Oh_g + o1) = hh; *(uint32_t*)(Ol_g + o1) = ll;
        }
    }
}

// ---------------- launch ------------------------------------------------------
extern "C" void kernel_launch(void* const* d_in, const int* in_sizes, int n_in,
                              void* d_out, int out_size)
{
    const float* x  = (const float*)d_in[0];
    const float* wq = (const float*)d_in[1];
    const float* wk = (const float*)d_in[2];
    const float* wv = (const float*)d_in[3];
    const float* wo = (const float*)d_in[4];
    float* out = (float*)d_out;

    float *pQf, *pKf, *pVf;
    __half *pXh, *pXl, *pWqh, *pWql, *pWkh, *pWkl, *pWvh, *pWvl, *pWoh, *pWol;
    __half *pQh, *pQl, *pKh, *pKl, *pVth, *pVtl, *pOh, *pOl;
    cudaGetSymbolAddress((void**)&pQf, g_Qf);
    cudaGetSymbolAddress((void**)&pKf, g_Kf);
    cudaGetSymbolAddress((void**)&pVf, g_Vf);
    cudaGetSymbolAddress((void**)&pXh, g_Xh);   cudaGetSymbolAddress((void**)&pXl, g_Xl);
    cudaGetSymbolAddress((void**)&pWqh, g_Wqh); cudaGetSymbolAddress((void**)&pWql, g_Wql);
    cudaGetSymbolAddress((void**)&pWkh, g_Wkh); cudaGetSymbolAddress((void**)&pWkl, g_Wkl);
    cudaGetSymbolAddress((void**)&pWvh, g_Wvh); cudaGetSymbolAddress((void**)&pWvl, g_Wvl);
    cudaGetSymbolAddress((void**)&pWoh, g_Woh); cudaGetSymbolAddress((void**)&pWol, g_Wol);
    cudaGetSymbolAddress((void**)&pQh, g_Qh);   cudaGetSymbolAddress((void**)&pQl, g_Ql);
    cudaGetSymbolAddress((void**)&pKh, g_Kh2);  cudaGetSymbolAddress((void**)&pKl, g_Kl2);
    cudaGetSymbolAddress((void**)&pVth, g_Vth); cudaGetSymbolAddress((void**)&pVtl, g_Vtl);
    cudaGetSymbolAddress((void**)&pOh, g_Oh);   cudaGetSymbolAddress((void**)&pOl, g_Ol);

    cudaFuncSetAttribute(gemm_h3, cudaFuncAttributeMaxDynamicSharedMemorySize, GS_BYTES);
    cudaFuncSetAttribute(flash_attn_h3, cudaFuncAttributeMaxDynamicSharedMemorySize, FA_SMEM_BYTES);

    // 1) split inputs/weights to fp16 hi/lo
    split_f32<<<(M_*D_/4)/256,   256>>>(x,  pXh,  pXl,  M_*D_/4);
    split_f32<<<(D_*D_/4)/256,   256>>>(wq, pWqh, pWql, D_*D_/4);
    split_f32<<<(KVD_*D_/4)/256, 256>>>(wk, pWkh, pWkl, KVD_*D_/4);
    split_f32<<<(KVD_*D_/4)/256, 256>>>(wv, pWvh, pWvl, KVD_*D_/4);
    split_f32<<<(D_*D_/4)/256,   256>>>(wo, pWoh, pWol, D_*D_/4);

    // 2) QKV projections (f32 out)
    gemm_h3<<<dim3(D_/128,   M_/128), 256, GS_BYTES>>>(pXh, pXl, pWqh, pWql, pQf, M_, D_,   D_);
    gemm_h3<<<dim3(KVD_/128, M_/128), 256, GS_BYTES>>>(pXh, pXl, pWkh, pWkl, pKf, M_, KVD_, D_);
    gemm_h3<<<dim3(KVD_/128, M_/128), 256, GS_BYTES>>>(pXh, pXl, pWvh, pWvl, pVf, M_, KVD_, D_);

    // 3) RoPE + split (Q pre-scaled), V transpose + split
    const float scale = 0.08838834764831845f;
    rope_split<<<(M_*H_*32)/256,  256>>>(pQf, pQh, pQl, H_,  scale, M_*H_*32);
    rope_split<<<(M_*KV_*32)/256, 256>>>(pKf, pKh, pKl, KV_, 1.0f,  M_*KV_*32);
    vtrans_split<<<dim3(T_/32, KVD_/32, B_), dim3(32, 8)>>>(pVf, pVth, pVtl);

    // 4) attention
    flash_attn_h3<<<dim3(T_/64, H_, B_), 256, FA_SMEM_BYTES>>>(
        pQh, pQl, pKh, pKl, pVth, pVtl, pOh, pOl);

    // 5) output projection
    gemm_h3<<<dim3(D_/128, M_/128), 256, GS_BYTES>>>(pOh, pOl, pWoh, pWol, out, M_, D_, D_);
}

// round 7
// speedup vs baseline: 4.4838x; 1.1898x over previous
#include <cuda_runtime.h>
#include <cuda_fp16.h>
#include <cstdint>
#include <math.h>

#define B_  2
#define T_  2048
#define D_  2048
#define H_  16
#define KV_ 4
#define HD_ 128
#define M_  (B_*T_)    // 4096
#define KVD_ (KV_*HD_) // 512
#define NQKV 3072      // packed Q(2048) + K(512) + V(512)

// ---------------- scratch ----------------------------------------------------
__device__ float  g_QKVf[M_ * NQKV];          // packed projection output
__device__ __half g_Xh[M_*D_];
__device__ __half g_W3h[NQKV*D_], g_W3l[NQKV*D_];
__device__ __half g_Woh[D_*D_],   g_Wol[D_*D_];
__device__ __half g_Qh[M_*D_],    g_Ql[M_*D_];
__device__ __half g_Kh2[M_*KVD_], g_Kl2[M_*KVD_];
__device__ __half g_Vth[M_*KVD_], g_Vtl[M_*KVD_];  // [(b*KV+g)*128+d][T]
__device__ __half g_Oh[M_*D_];

// ---------------- helpers -----------------------------------------------------
__device__ __forceinline__ void cvt2(float x, float y, uint32_t& h, uint32_t& l) {
    __half2 hh = __floats2half2_rn(x, y);
    float2 hf = __half22float2(hh);
    __half2 ll = __floats2half2_rn(x - hf.x, y - hf.y);
    h = *reinterpret_cast<uint32_t*>(&hh);
    l = *reinterpret_cast<uint32_t*>(&ll);
}
__device__ __forceinline__ uint32_t cvth(float x, float y) {
    __half2 hh = __floats2half2_rn(x, y);
    return *reinterpret_cast<uint32_t*>(&hh);
}
__device__ __forceinline__ void mma_f16(float* c, const uint32_t* a, const uint32_t* b) {
    asm volatile(
        "mma.sync.aligned.m16n8k16.row.col.f32.f16.f16.f32 "
        "{%0,%1,%2,%3}, {%4,%5,%6,%7}, {%8,%9}, {%0,%1,%2,%3};"
        : "+f"(c[0]), "+f"(c[1]), "+f"(c[2]), "+f"(c[3])
        : "r"(a[0]), "r"(a[1]), "r"(a[2]), "r"(a[3]), "r"(b[0]), "r"(b[1]));
}
__device__ __forceinline__ uint32_t s2u(const void* p) {
    uint32_t a;
    asm("{ .reg .u64 t; cvta.to.shared.u64 t, %1; cvt.u32.u64 %0, t; }" : "=r"(a) : "l"(p));
    return a;
}
#define CP16(dst, src) asm volatile("cp.async.cg.shared.global [%0], [%1], 16;" :: "r"(dst), "l"(src))
#define CPC   asm volatile("cp.async.commit_group;" ::: "memory")
#define CPW0  asm volatile("cp.async.wait_group 0;" ::: "memory")
#define CPW1  asm volatile("cp.async.wait_group 1;" ::: "memory")

// ---------------- pre-split kernels -------------------------------------------
__global__ void split_f32(const float* __restrict__ X,
                          __half* __restrict__ Xh, __half* __restrict__ Xl, int n4)
{
    int i = blockIdx.x * blockDim.x + threadIdx.x;
    if (i >= n4) return;
    float4 v = *(const float4*)(X + (size_t)i * 4);
    uint32_t h0, l0, h1, l1;
    cvt2(v.x, v.y, h0, l0);
    cvt2(v.z, v.w, h1, l1);
    *(uint2*)(Xh + (size_t)i * 4) = make_uint2(h0, h1);
    *(uint2*)(Xl + (size_t)i * 4) = make_uint2(l0, l1);
}
__global__ void split_hi(const float* __restrict__ X, __half* __restrict__ Xh, int n4)
{
    int i = blockIdx.x * blockDim.x + threadIdx.x;
    if (i >= n4) return;
    float4 v = *(const float4*)(X + (size_t)i * 4);
    *(uint2*)(Xh + (size_t)i * 4) = make_uint2(cvth(v.x, v.y), cvth(v.z, v.w));
}

// RoPE + split: reads f32 [m][in_ld] at column offset, writes dense hi/lo fp16.
__global__ void rope_split(const float* __restrict__ X,
                           __half* __restrict__ Xh, __half* __restrict__ Xl,
                           int nheads, float scale, int in_ld, int in_off, int total)
{
    int idx = blockIdx.x * blockDim.x + threadIdx.x;
    if (idx >= total) return;
    int j2 = idx & 31;
    int hh = (idx >> 5) % nheads;
    int m  = idx / (32 * nheads);
    int t  = m & (T_ - 1);

    size_t ri = (size_t)m * in_ld + in_off + hh * HD_;
    size_t ro = (size_t)m * (nheads * HD_) + hh * HD_;
    float2 a  = *(const float2*)(X + ri + j2*2);
    float2 bq = *(const float2*)(X + ri + 64 + j2*2);

    float inv0 = powf(10000.0f, -((float)(2 * (2*j2))     / 128.0f));
    float inv1 = powf(10000.0f, -((float)(2 * (2*j2 + 1)) / 128.0f));
    float s0, c0, s1, c1;
    sincosf((float)t * inv0, &s0, &c0);
    sincosf((float)t * inv1, &s1, &c1);

    float o0 = (a.x * c0 - bq.x * s0) * scale;
    float o1 = (a.y * c1 - bq.y * s1) * scale;
    float o2 = (bq.x * c0 + a.x * s0) * scale;
    float o3 = (bq.y * c1 + a.y * s1) * scale;

    uint32_t ph, pl;
    cvt2(o0, o1, ph, pl);
    *(uint32_t*)(Xh + ro + j2*2) = ph;
    *(uint32_t*)(Xl + ro + j2*2) = pl;
    cvt2(o2, o3, ph, pl);
    *(uint32_t*)(Xh + ro + 64 + j2*2) = ph;
    *(uint32_t*)(Xl + ro + 64 + j2*2) = pl;
}

// V transpose + split: packed QKVf col 2560+ -> [(b*KV+g)*128+d][t] fp16 hi/lo
__global__ void vtrans_split(const float* __restrict__ QKV,
                             __half* __restrict__ Vh, __half* __restrict__ Vl)
{
    __shared__ float tile[32][33];
    int bx = blockIdx.x, by = blockIdx.y, b = blockIdx.z;
    int tx = threadIdx.x, ty = threadIdx.y;
    #pragma unroll
    for (int i = 0; i < 4; i++) {
        int tt = bx*32 + ty + i*8;
        int dd = by*32 + tx;
        tile[ty + i*8][tx] = QKV[(size_t)(b*T_ + tt) * NQKV + 2560 + dd];
    }
    __syncthreads();
    #pragma unroll
    for (int i = 0; i < 4; i++) {
        int dd = by*32 + ty + i*8;
        int tt = bx*32 + tx;
        float v = tile[tx][ty + i*8];
        __half hv = __float2half_rn(v);
        __half lv = __float2half_rn(v - __half2float(hv));
        size_t o = (size_t)(b*KVD_ + dd) * T_ + tt;
        Vh[o] = hv; Vl[o] = lv;
    }
}

// ============================================================================
// 2-term fp16 GEMM: C[m,n] = Ah[m,:]*(Bh+Bl)[n,:]   (A one-sided fp16)
// CTA 128x128x32, 256 thr, warp tile m64 x n32, cp.async double-buffered.
// Smem: per stage 3 matrices x 128 rows x 20 u32. 61440 B total (3 CTAs/SM).
// ============================================================================
#define G2_BYTES (2*3*2560*4)

__global__ __launch_bounds__(256) void gemm_2t(
    const __half* __restrict__ Ah_g,
    const __half* __restrict__ Bh_g, const __half* __restrict__ Bl_g,
    float* __restrict__ C, int ldc, int K)
{
    extern __shared__ uint32_t su[];
    const uint32_t sb = s2u(su);
    const int tid = threadIdx.x, lane = tid & 31, w = tid >> 5;
    const int bm = blockIdx.y * 128, bn = blockIdx.x * 128;
    const int wm = (w & 1) * 64;     // 2 m positions
    const int wn = (w >> 1) * 32;    // 4 n positions
    const int g = lane >> 2, t = lane & 3;

    const int matid = tid >> 6;   // 0 Ah, 1 Bh, 2 Bl, 3 idle
    const __half* gp = (matid == 0) ? Ah_g : (matid == 1) ? Bh_g : Bl_g;
    const int rowb = (matid == 0) ? bm : bn;
    const int t64 = tid & 63;
    const int rb0 = t64 >> 2, cc = t64 & 3;
    const uint32_t dstb = sb + matid*10240 + rb0*80 + cc*16;
    const __half* srcb = gp + (size_t)(rowb + rb0) * K + cc * 8;
    const bool loader = (matid < 3);

    float acc[4][4][4];
    #pragma unroll
    for (int mb = 0; mb < 4; mb++)
        #pragma unroll
        for (int nb = 0; nb < 4; nb++)
            #pragma unroll
            for (int i = 0; i < 4; i++) acc[mb][nb][i] = 0.f;

    if (loader) {
        #pragma unroll
        for (int i = 0; i < 8; i++)
            CP16(dstb + i*1280, srcb + (size_t)(16*i) * K);
    }
    CPC;

    const int NT = K >> 5;
    for (int kt = 0; kt < NT; kt++) {
        const int stg = kt & 1;
        CPW0;
        __syncthreads();
        if (kt + 1 < NT && loader) {
            const __half* s = srcb + (kt + 1) * 32;
            const uint32_t d2 = dstb + (stg ^ 1) * 30720;
            #pragma unroll
            for (int i = 0; i < 8; i++)
                CP16(d2 + i*1280, s + (size_t)(16*i) * K);
        }
        CPC;

        uint32_t* Ahs = su + stg * 7680;
        uint32_t* Bhs = Ahs + 2560;
        uint32_t* Bls = Ahs + 5120;

        #pragma unroll
        for (int ks = 0; ks < 2; ks++) {
            const int kp = ks * 8 + t;
            uint32_t ah[4][4];
            #pragma unroll
            for (int mb = 0; mb < 4; mb++) {
                int r = wm + mb * 16 + g;
                ah[mb][0] = Ahs[r*20 + kp];     ah[mb][1] = Ahs[(r+8)*20 + kp];
                ah[mb][2] = Ahs[r*20 + kp + 4]; ah[mb][3] = Ahs[(r+8)*20 + kp + 4];
            }
            #pragma unroll
            for (int nb = 0; nb < 4; nb++) {
                int n = wn + nb * 8 + g;
                uint32_t bh2[2], bl2[2];
                bh2[0] = Bhs[n*20 + kp]; bh2[1] = Bhs[n*20 + kp + 4];
                bl2[0] = Bls[n*20 + kp]; bl2[1] = Bls[n*20 + kp + 4];
                #pragma unroll
                for (int mb = 0; mb < 4; mb++) {
                    mma_f16(acc[mb][nb], ah[mb], bh2);
                    mma_f16(acc[mb][nb], ah[mb], bl2);
                }
            }
        }
    }

    #pragma unroll
    for (int mb = 0; mb < 4; mb++) {
        int r0 = bm + wm + mb * 16 + g;
        #pragma unroll
        for (int nb = 0; nb < 4; nb++) {
            int ccn = bn + wn + nb * 8 + 2 * t;
            *(float2*)(C + (size_t)r0 * ldc + ccn)       = make_float2(acc[mb][nb][0], acc[mb][nb][1]);
            *(float2*)(C + (size_t)(r0 + 8) * ldc + ccn) = make_float2(acc[mb][nb][2], acc[mb][nb][3]);
        }
    }
}

// ============================================================================
// fp16-split flash attention (3-term), cp.async pipelined K/V
// ============================================================================
#define AP 68
#define QH_OFF 0
#define QL_OFF (QH_OFF + 64*AP)
#define KH_OFF (QL_OFF + 64*AP)
#define KL_OFF (KH_OFF + 128*AP)
#define VH_OFF (KL_OFF + 128*AP)
#define VL_OFF (VH_OFF + 128*AP)
#define PH_OFF (VL_OFF + 128*AP)
#define PL_OFF (PH_OFF + 64*AP)
#define ST_OFF (PL_OFF + 64*AP)
#define FA_SMEM_BYTES ((ST_OFF + 64*3 + 4*64*2) * 4)   // 211712 B

__global__ __launch_bounds__(256) void flash_attn_h3(
    const __half* __restrict__ Qh_g, const __half* __restrict__ Ql_g,
    const __half* __restrict__ Kh_g, const __half* __restrict__ Kl_g,
    const __half* __restrict__ Vh_g, const __half* __restrict__ Vl_g,
    __half* __restrict__ Oh_g)
{
    extern __shared__ uint32_t su[];
    const uint32_t sb = s2u(su);
    uint32_t* Ph = su + PH_OFF;
    uint32_t* Pl = su + PL_OFF;
    float* m_s  = (float*)(su + ST_OFF);
    float* l_s  = m_s + 64;
    float* rs_s = l_s + 64;
    float* pmax = rs_s + 64;
    float* psum = pmax + 4*64;

    const int tid = threadIdx.x, lane = tid & 31, w = tid >> 5;
    const int qt = blockIdx.x, h = blockIdx.y, b = blockIdx.z;
    const int gq = h >> 2;
    const int q0 = qt * 64;
    const int wm = (w & 1) * 32;
    const int wn = (w >> 1) * 32;
    const int g = lane >> 2, t = lane & 3;

    const int vm = tid >> 7;
    const int t128 = tid & 127;
    const int qr = t128 >> 4, qc = t128 & 15;

    auto issueK = [&](int s0k) {
        const __half* src = (vm ? Kl_g : Kh_g) + (size_t)(b*T_ + s0k + qr) * KVD_ + gq*HD_ + qc*8;
        uint32_t dst = sb + (uint32_t)(KH_OFF + vm*(128*AP))*4 + qr*272 + qc*16;
        #pragma unroll
        for (int i = 0; i < 16; i++)
            CP16(dst + i*8*272, src + (size_t)(8*i) * KVD_);
    };
    auto issueV = [&](int s0v) {
        const __half* src = (vm ? Vl_g : Vh_g) + ((size_t)(b*KV_ + gq)*HD_ + qr) * T_ + s0v + qc*8;
        uint32_t dst = sb + (uint32_t)(VH_OFF + vm*(128*AP))*4 + qr*272 + qc*16;
        #pragma unroll
        for (int i = 0; i < 16; i++)
            CP16(dst + i*8*272, src + (size_t)(8*i) * T_);
    };

    {
        const __half* src = (vm ? Ql_g : Qh_g) + (size_t)(b*T_ + q0 + qr) * D_ + h*HD_ + qc*8;
        uint32_t dst = sb + (uint32_t)(QH_OFF + vm*(64*AP))*4 + qr*272 + qc*16;
        #pragma unroll
        for (int i = 0; i < 8; i++)
            CP16(dst + i*8*272, src + (size_t)(8*i) * D_);
        issueK(0);
    }
    CPC;
    issueV(0);
    CPC;

    if (tid < 64) { m_s[tid] = -INFINITY; l_s[tid] = 0.f; }

    float acc[2][4][4];
    #pragma unroll
    for (int mb = 0; mb < 2; mb++)
        #pragma unroll
        for (int nb = 0; nb < 4; nb++)
            #pragma unroll
            for (int i = 0; i < 4; i++) acc[mb][nb][i] = 0.f;

    uint32_t* Qhs = su + QH_OFF;  uint32_t* Qls = su + QL_OFF;
    uint32_t* Khs = su + KH_OFF;  uint32_t* Kls = su + KL_OFF;
    uint32_t* Vhs = su + VH_OFF;  uint32_t* Vls = su + VL_OFF;

    for (int it = 0; it < 16; it++) {
        CPW1;
        __syncthreads();

        // ---- S = Q K^T ----
        float sfr[2][4][4];
        #pragma unroll
        for (int mb = 0; mb < 2; mb++)
            #pragma unroll
            for (int nb = 0; nb < 4; nb++)
                #pragma unroll
                for (int i = 0; i < 4; i++) sfr[mb][nb][i] = 0.f;

        #pragma unroll
        for (int k16 = 0; k16 < 8; k16++) {
            const int kp = k16 * 8 + t;
            uint32_t ah[2][4], al[2][4];
            #pragma unroll
            for (int mb = 0; mb < 2; mb++) {
                int r = wm + mb * 16 + g;
                ah[mb][0] = Qhs[r*AP + kp];     ah[mb][1] = Qhs[(r+8)*AP + kp];
                ah[mb][2] = Qhs[r*AP + kp + 4]; ah[mb][3] = Qhs[(r+8)*AP + kp + 4];
                al[mb][0] = Qls[r*AP + kp];     al[mb][1] = Qls[(r+8)*AP + kp];
                al[mb][2] = Qls[r*AP + kp + 4]; al[mb][3] = Qls[(r+8)*AP + kp + 4];
            }
            #pragma unroll
            for (int nb = 0; nb < 4; nb++) {
                int n = wn + nb * 8 + g;
                uint32_t bh2[2], bl2[2];
                bh2[0] = Khs[n*AP + kp]; bh2[1] = Khs[n*AP + kp + 4];
                bl2[0] = Kls[n*AP + kp]; bl2[1] = Kls[n*AP + kp + 4];
                #pragma unroll
                for (int mb = 0; mb < 2; mb++) {
                    mma_f16(sfr[mb][nb], ah[mb], bh2);
                    mma_f16(sfr[mb][nb], ah[mb], bl2);
                    mma_f16(sfr[mb][nb], al[mb], bh2);
                }
            }
        }

        // ---- row max ----
        #pragma unroll
        for (int mb = 0; mb < 2; mb++) {
            float m0 = -INFINITY, m1 = -INFINITY;
            #pragma unroll
            for (int nb = 0; nb < 4; nb++) {
                m0 = fmaxf(m0, fmaxf(sfr[mb][nb][0], sfr[mb][nb][1]));
                m1 = fmaxf(m1, fmaxf(sfr[mb][nb][2], sfr[mb][nb][3]));
            }
            m0 = fmaxf(m0, __shfl_xor_sync(0xffffffffu, m0, 1));
            m0 = fmaxf(m0, __shfl_xor_sync(0xffffffffu, m0, 2));
            m1 = fmaxf(m1, __shfl_xor_sync(0xffffffffu, m1, 1));
            m1 = fmaxf(m1, __shfl_xor_sync(0xffffffffu, m1, 2));
            if (t == 0) {
                pmax[(w>>1)*64 + wm + mb*16 + g    ] = m0;
                pmax[(w>>1)*64 + wm + mb*16 + g + 8] = m1;
            }
        }
        __syncthreads();

        if (it + 1 < 16) issueK((it + 1) * 128);
        CPC;

        if (tid < 64) {
            int r = tid;
            float mt = fmaxf(fmaxf(pmax[r], pmax[64+r]), fmaxf(pmax[128+r], pmax[192+r]));
            float m_old = m_s[r];
            float m_new = fmaxf(m_old, mt);
            float rs = __expf(m_old - m_new);
            rs_s[r] = rs; m_s[r] = m_new; l_s[r] *= rs;
        }
        __syncthreads();

        // ---- exp, P->smem split, partial sums; rescale acc ----
        float ps[2][2] = {{0.f,0.f},{0.f,0.f}};
        #pragma unroll
        for (int mb = 0; mb < 2; mb++) {
            int row0 = wm + mb*16 + g;
            float m0 = m_s[row0], m1 = m_s[row0 + 8];
            #pragma unroll
            for (int nb = 0; nb < 4; nb++) {
                int pp = (wn >> 1) + nb*4 + t;
                float p0 = __expf(sfr[mb][nb][0] - m0);
                float p1 = __expf(sfr[mb][nb][1] - m0);
                float p2 = __expf(sfr[mb][nb][2] - m1);
                float p3 = __expf(sfr[mb][nb][3] - m1);
                ps[mb][0] += p0 + p1;
                ps[mb][1] += p2 + p3;
                uint32_t hh, ll;
                cvt2(p0, p1, hh, ll);
                Ph[row0*AP + pp] = hh; Pl[row0*AP + pp] = ll;
                cvt2(p2, p3, hh, ll);
                Ph[(row0+8)*AP + pp] = hh; Pl[(row0+8)*AP + pp] = ll;
            }
            ps[mb][0] += __shfl_xor_sync(0xffffffffu, ps[mb][0], 1);
            ps[mb][0] += __shfl_xor_sync(0xffffffffu, ps[mb][0], 2);
            ps[mb][1] += __shfl_xor_sync(0xffffffffu, ps[mb][1], 1);
            ps[mb][1] += __shfl_xor_sync(0xffffffffu, ps[mb][1], 2);
            if (t == 0) {
                psum[(w>>1)*64 + wm + mb*16 + g    ] = ps[mb][0];
                psum[(w>>1)*64 + wm + mb*16 + g + 8] = ps[mb][1];
            }
        }
        #pragma unroll
        for (int mb = 0; mb < 2; mb++) {
            int row0 = wm + mb*16 + g;
            float r0 = rs_s[row0], r1 = rs_s[row0 + 8];
            #pragma unroll
            for (int nb = 0; nb < 4; nb++) {
                acc[mb][nb][0] *= r0; acc[mb][nb][1] *= r0;
                acc[mb][nb][2] *= r1; acc[mb][nb][3] *= r1;
            }
        }
        if (it < 15) { CPW1; } else { CPW0; }
        __syncthreads();
        if (tid < 64)
            l_s[tid] += psum[tid] + psum[64+tid] + psum[128+tid] + psum[192+tid];

        // ---- O += P V ----
        #pragma unroll
        for (int k16 = 0; k16 < 8; k16++) {
            const int kp = k16 * 8 + t;
            uint32_t ah[2][4], al[2][4];
            #pragma unroll
            for (int mb = 0; mb < 2; mb++) {
                int r = wm + mb * 16 + g;
                ah[mb][0] = Ph[r*AP + kp];     ah[mb][1] = Ph[(r+8)*AP + kp];
                ah[mb][2] = Ph[r*AP + kp + 4]; ah[mb][3] = Ph[(r+8)*AP + kp + 4];
                al[mb][0] = Pl[r*AP + kp];     al[mb][1] = Pl[(r+8)*AP + kp];
                al[mb][2] = Pl[r*AP + kp + 4]; al[mb][3] = Pl[(r+8)*AP + kp + 4];
            }
            #pragma unroll
            for (int nb = 0; nb < 4; nb++) {
                int n = wn + nb * 8 + g;
                uint32_t bh2[2], bl2[2];
                bh2[0] = Vhs[n*AP + kp]; bh2[1] = Vhs[n*AP + kp + 4];
                bl2[0] = Vls[n*AP + kp]; bl2[1] = Vls[n*AP + kp + 4];
                #pragma unroll
                for (int mb = 0; mb < 2; mb++) {
                    mma_f16(acc[mb][nb], ah[mb], bh2);
                    mma_f16(acc[mb][nb], ah[mb], bl2);
                    mma_f16(acc[mb][nb], al[mb], bh2);
                }
            }
        }
        __syncthreads();

        if (it + 1 < 16) issueV((it + 1) * 128);
        CPC;
    }

    // ---- epilogue: normalize, write fp16 hi only ----
    #pragma unroll
    for (int mb = 0; mb < 2; mb++) {
        int row0 = wm + mb*16 + g;
        float inv0 = 1.0f / l_s[row0];
        float inv1 = 1.0f / l_s[row0 + 8];
        #pragma unroll
        for (int nb = 0; nb < 4; nb++) {
            int col = h*HD_ + wn + nb*8 + 2*t;
            size_t o0 = (size_t)(b*T_ + q0 + row0) * D_ + col;
            size_t o1 = (size_t)(b*T_ + q0 + row0 + 8) * D_ + col;
            *(uint32_t*)(Oh_g + o0) = cvth(acc[mb][nb][0]*inv0, acc[mb][nb][1]*inv0);
            *(uint32_t*)(Oh_g + o1) = cvth(acc[mb][nb][2]*inv1, acc[mb][nb][3]*inv1);
        }
    }
}

// ---------------- launch ------------------------------------------------------
extern "C" void kernel_launch(void* const* d_in, const int* in_sizes, int n_in,
                              void* d_out, int out_size)
{
    const float* x  = (const float*)d_in[0];
    const float* wq = (const float*)d_in[1];
    const float* wk = (const float*)d_in[2];
    const float* wv = (const float*)d_in[3];
    const float* wo = (const float*)d_in[4];
    float* out = (float*)d_out;

    float *pQKV;
    __half *pXh, *pW3h, *pW3l, *pWoh, *pWol;
    __half *pQh, *pQl, *pKh, *pKl, *pVth, *pVtl, *pOh;
    cudaGetSymbolAddress((void**)&pQKV, g_QKVf);
    cudaGetSymbolAddress((void**)&pXh, g_Xh);
    cudaGetSymbolAddress((void**)&pW3h, g_W3h); cudaGetSymbolAddress((void**)&pW3l, g_W3l);
    cudaGetSymbolAddress((void**)&pWoh, g_Woh); cudaGetSymbolAddress((void**)&pWol, g_Wol);
    cudaGetSymbolAddress((void**)&pQh, g_Qh);   cudaGetSymbolAddress((void**)&pQl, g_Ql);
    cudaGetSymbolAddress((void**)&pKh, g_Kh2);  cudaGetSymbolAddress((void**)&pKl, g_Kl2);
    cudaGetSymbolAddress((void**)&pVth, g_Vth); cudaGetSymbolAddress((void**)&pVtl, g_Vtl);
    cudaGetSymbolAddress((void**)&pOh, g_Oh);

    cudaFuncSetAttribute(gemm_2t, cudaFuncAttributeMaxDynamicSharedMemorySize, G2_BYTES);
    cudaFuncSetAttribute(flash_attn_h3, cudaFuncAttributeMaxDynamicSharedMemorySize, FA_SMEM_BYTES);

    // 1) splits: x -> hi only; weights -> hi/lo (wq/wk/wv packed into W3)
    split_hi<<<(M_*D_/4)/256, 256>>>(x, pXh, M_*D_/4);
    split_f32<<<(D_*D_/4)/256,   256>>>(wq, pW3h,                      pW3l,                      D_*D_/4);
    split_f32<<<(KVD_*D_/4)/256, 256>>>(wk, pW3h + (size_t)2048*2048,  pW3l + (size_t)2048*2048,  KVD_*D_/4);
    split_f32<<<(KVD_*D_/4)/256, 256>>>(wv, pW3h + (size_t)2560*2048,  pW3l + (size_t)2560*2048,  KVD_*D_/4);
    split_f32<<<(D_*D_/4)/256,   256>>>(wo, pWoh, pWol, D_*D_/4);

    // 2) fused QKV projection (one GEMM, packed output)
    gemm_2t<<<dim3(NQKV/128, M_/128), 256, G2_BYTES>>>(pXh, pW3h, pW3l, pQKV, NQKV, D_);

    // 3) RoPE + split (Q pre-scaled), V transpose + split (from packed buffer)
    const float scale = 0.08838834764831845f;
    rope_split<<<(M_*H_*32)/256,  256>>>(pQKV, pQh, pQl, H_,  scale, NQKV, 0,    M_*H_*32);
    rope_split<<<(M_*KV_*32)/256, 256>>>(pQKV, pKh, pKl, KV_, 1.0f,  NQKV, 2048, M_*KV_*32);
    vtrans_split<<<dim3(T_/32, KVD_/32, B_), dim3(32, 8)>>>(pQKV, pVth, pVtl);

    // 4) attention (3-term, fp16-hi output)
    flash_attn_h3<<<dim3(T_/64, H_, B_), 256, FA_SMEM_BYTES>>>(
        pQh, pQl, pKh, pKl, pVth, pVtl, pOh);

    // 5) output projection (2-term)
    gemm_2t<<<dim3(D_/128, M_/128), 256, G2_BYTES>>>(pOh, pWoh, pWol, out, D_, D_);
}

// round 8
// speedup vs baseline: 4.8171x; 1.0743x over previous
#include <cuda_runtime.h>
#include <cuda_fp16.h>
#include <cstdint>
#include <math.h>

#define B_  2
#define T_  2048
#define D_  2048
#define H_  16
#define KV_ 4
#define HD_ 128
#define M_  (B_*T_)    // 4096
#define KVD_ (KV_*HD_) // 512
#define NQKV 3072      // packed Q(2048) + K(512) + V(512)

// ---------------- scratch ----------------------------------------------------
__device__ float  g_QKVf[M_ * NQKV];
__device__ __half g_Xh[M_*D_];
__device__ __half g_W3h[NQKV*D_], g_W3l[NQKV*D_];
__device__ __half g_Woh[D_*D_],   g_Wol[D_*D_];
__device__ __half g_Qh[M_*D_],    g_Ql[M_*D_];
__device__ __half g_Kh2[M_*KVD_], g_Kl2[M_*KVD_];
__device__ __half g_Vth[M_*KVD_], g_Vtl[M_*KVD_];  // [(b*KV+g)*128+d][T]
__device__ __half g_Oh[M_*D_];

// ---------------- helpers -----------------------------------------------------
__device__ __forceinline__ void cvt2(float x, float y, uint32_t& h, uint32_t& l) {
    __half2 hh = __floats2half2_rn(x, y);
    float2 hf = __half22float2(hh);
    __half2 ll = __floats2half2_rn(x - hf.x, y - hf.y);
    h = *reinterpret_cast<uint32_t*>(&hh);
    l = *reinterpret_cast<uint32_t*>(&ll);
}
__device__ __forceinline__ uint32_t cvth(float x, float y) {
    __half2 hh = __floats2half2_rn(x, y);
    return *reinterpret_cast<uint32_t*>(&hh);
}
__device__ __forceinline__ void mma_f16(float* c, const uint32_t* a, const uint32_t* b) {
    asm volatile(
        "mma.sync.aligned.m16n8k16.row.col.f32.f16.f16.f32 "
        "{%0,%1,%2,%3}, {%4,%5,%6,%7}, {%8,%9}, {%0,%1,%2,%3};"
        : "+f"(c[0]), "+f"(c[1]), "+f"(c[2]), "+f"(c[3])
        : "r"(a[0]), "r"(a[1]), "r"(a[2]), "r"(a[3]), "r"(b[0]), "r"(b[1]));
}
__device__ __forceinline__ uint32_t s2u(const void* p) {
    uint32_t a;
    asm("{ .reg .u64 t; cvta.to.shared.u64 t, %1; cvt.u32.u64 %0, t; }" : "=r"(a) : "l"(p));
    return a;
}
#define LDSM4(r0, r1, r2, r3, addr) \
    asm volatile("ldmatrix.sync.aligned.m8n8.x4.shared.b16 {%0,%1,%2,%3}, [%4];" \
        : "=r"(r0), "=r"(r1), "=r"(r2), "=r"(r3) : "r"(addr))
#define CP16(dst, src) asm volatile("cp.async.cg.shared.global [%0], [%1], 16;" :: "r"(dst), "l"(src))
#define CPC   asm volatile("cp.async.commit_group;" ::: "memory")
#define CPW0  asm volatile("cp.async.wait_group 0;" ::: "memory")
#define CPW1  asm volatile("cp.async.wait_group 1;" ::: "memory")

// ---------------- pre-split kernels -------------------------------------------
__global__ void split_f32(const float* __restrict__ X,
                          __half* __restrict__ Xh, __half* __restrict__ Xl, int n4)
{
    int i = blockIdx.x * blockDim.x + threadIdx.x;
    if (i >= n4) return;
    float4 v = *(const float4*)(X + (size_t)i * 4);
    uint32_t h0, l0, h1, l1;
    cvt2(v.x, v.y, h0, l0);
    cvt2(v.z, v.w, h1, l1);
    *(uint2*)(Xh + (size_t)i * 4) = make_uint2(h0, h1);
    *(uint2*)(Xl + (size_t)i * 4) = make_uint2(l0, l1);
}
__global__ void split_hi(const float* __restrict__ X, __half* __restrict__ Xh, int n4)
{
    int i = blockIdx.x * blockDim.x + threadIdx.x;
    if (i >= n4) return;
    float4 v = *(const float4*)(X + (size_t)i * 4);
    *(uint2*)(Xh + (size_t)i * 4) = make_uint2(cvth(v.x, v.y), cvth(v.z, v.w));
}

__global__ void rope_split(const float* __restrict__ X,
                           __half* __restrict__ Xh, __half* __restrict__ Xl,
                           int nheads, float scale, int in_ld, int in_off, int total)
{
    int idx = blockIdx.x * blockDim.x + threadIdx.x;
    if (idx >= total) return;
    int j2 = idx & 31;
    int hh = (idx >> 5) % nheads;
    int m  = idx / (32 * nheads);
    int t  = m & (T_ - 1);

    size_t ri = (size_t)m * in_ld + in_off + hh * HD_;
    size_t ro = (size_t)m * (nheads * HD_) + hh * HD_;
    float2 a  = *(const float2*)(X + ri + j2*2);
    float2 bq = *(const float2*)(X + ri + 64 + j2*2);

    float inv0 = powf(10000.0f, -((float)(2 * (2*j2))     / 128.0f));
    float inv1 = powf(10000.0f, -((float)(2 * (2*j2 + 1)) / 128.0f));
    float s0, c0, s1, c1;
    sincosf((float)t * inv0, &s0, &c0);
    sincosf((float)t * inv1, &s1, &c1);

    float o0 = (a.x * c0 - bq.x * s0) * scale;
    float o1 = (a.y * c1 - bq.y * s1) * scale;
    float o2 = (bq.x * c0 + a.x * s0) * scale;
    float o3 = (bq.y * c1 + a.y * s1) * scale;

    uint32_t ph, pl;
    cvt2(o0, o1, ph, pl);
    *(uint32_t*)(Xh + ro + j2*2) = ph;
    *(uint32_t*)(Xl + ro + j2*2) = pl;
    cvt2(o2, o3, ph, pl);
    *(uint32_t*)(Xh + ro + 64 + j2*2) = ph;
    *(uint32_t*)(Xl + ro + 64 + j2*2) = pl;
}

__global__ void vtrans_split(const float* __restrict__ QKV,
                             __half* __restrict__ Vh, __half* __restrict__ Vl)
{
    __shared__ float tile[32][33];
    int bx = blockIdx.x, by = blockIdx.y, b = blockIdx.z;
    int tx = threadIdx.x, ty = threadIdx.y;
    #pragma unroll
    for (int i = 0; i < 4; i++) {
        int tt = bx*32 + ty + i*8;
        int dd = by*32 + tx;
        tile[ty + i*8][tx] = QKV[(size_t)(b*T_ + tt) * NQKV + 2560 + dd];
    }
    __syncthreads();
    #pragma unroll
    for (int i = 0; i < 4; i++) {
        int dd = by*32 + ty + i*8;
        int tt = bx*32 + tx;
        float v = tile[tx][ty + i*8];
        __half hv = __float2half_rn(v);
        __half lv = __float2half_rn(v - __half2float(hv));
        size_t o = (size_t)(b*KVD_ + dd) * T_ + tt;
        Vh[o] = hv; Vl[o] = lv;
    }
}

// ============================================================================
// 2-term fp16 GEMM with ldmatrix fragment loads.
// CTA 128x128x32, 256 thr, warp tile m64 x n32, cp.async double-buffered.
// Smem rows: 40 halves (80 B); 8-row LDSM offsets mod 128B all distinct.
// ============================================================================
#define G2_BYTES (2*3*2560*4)

__global__ __launch_bounds__(256) void gemm_2t(
    const __half* __restrict__ Ah_g,
    const __half* __restrict__ Bh_g, const __half* __restrict__ Bl_g,
    float* __restrict__ C, int ldc, int K)
{
    extern __shared__ uint32_t su[];
    const uint32_t sb = s2u(su);
    const int tid = threadIdx.x, lane = tid & 31, w = tid >> 5;
    const int bm = blockIdx.y * 128, bn = blockIdx.x * 128;
    const int wm = (w & 1) * 64;
    const int wn = (w >> 1) * 32;
    const int g = lane >> 2, t = lane & 3;

    const int matid = tid >> 6;   // 0 Ah, 1 Bh, 2 Bl, 3 idle
    const __half* gp = (matid == 0) ? Ah_g : (matid == 1) ? Bh_g : Bl_g;
    const int rowb = (matid == 0) ? bm : bn;
    const int t64 = tid & 63;
    const int rb0 = t64 >> 2, cc = t64 & 3;
    const uint32_t dstb = sb + matid*10240 + rb0*80 + cc*16;
    const __half* srcb = gp + (size_t)(rowb + rb0) * K + cc * 8;
    const bool loader = (matid < 3);

    // ldmatrix per-lane base addresses
    const int arow = wm + ((lane >> 3) & 1) * 8 + (lane & 7);
    const uint32_t aBase = sb + arow * 80 + (lane >> 4) * 16;           // Ah at offset 0
    const int brow = wn + (lane >> 4) * 8 + (lane & 7);
    const uint32_t bBase = sb + 10240 + brow * 80 + ((lane >> 3) & 1) * 16;

    float acc[4][4][4];
    #pragma unroll
    for (int mb = 0; mb < 4; mb++)
        #pragma unroll
        for (int nb = 0; nb < 4; nb++)
            #pragma unroll
            for (int i = 0; i < 4; i++) acc[mb][nb][i] = 0.f;

    if (loader) {
        #pragma unroll
        for (int i = 0; i < 8; i++)
            CP16(dstb + i*1280, srcb + (size_t)(16*i) * K);
    }
    CPC;

    const int NT = K >> 5;
    for (int kt = 0; kt < NT; kt++) {
        const int stg = kt & 1;
        const uint32_t stgoff = stg * 30720;
        CPW0;
        __syncthreads();
        if (kt + 1 < NT && loader) {
            const __half* s = srcb + (kt + 1) * 32;
            const uint32_t d2 = dstb + (stg ^ 1) * 30720;
            #pragma unroll
            for (int i = 0; i < 8; i++)
                CP16(d2 + i*1280, s + (size_t)(16*i) * K);
        }
        CPC;

        #pragma unroll
        for (int ks = 0; ks < 2; ks++) {
            uint32_t ah[4][4], bh[4][2], bl[4][2];
            #pragma unroll
            for (int mb = 0; mb < 4; mb++)
                LDSM4(ah[mb][0], ah[mb][1], ah[mb][2], ah[mb][3],
                      aBase + stgoff + mb*1280 + ks*32);
            #pragma unroll
            for (int nbp = 0; nbp < 2; nbp++) {
                LDSM4(bh[2*nbp][0], bh[2*nbp][1], bh[2*nbp+1][0], bh[2*nbp+1][1],
                      bBase + stgoff + nbp*1280 + ks*32);
                LDSM4(bl[2*nbp][0], bl[2*nbp][1], bl[2*nbp+1][0], bl[2*nbp+1][1],
                      bBase + stgoff + 10240 + nbp*1280 + ks*32);
            }
            #pragma unroll
            for (int nb = 0; nb < 4; nb++)
                #pragma unroll
                for (int mb = 0; mb < 4; mb++) {
                    mma_f16(acc[mb][nb], ah[mb], bh[nb]);
                    mma_f16(acc[mb][nb], ah[mb], bl[nb]);
                }
        }
    }

    #pragma unroll
    for (int mb = 0; mb < 4; mb++) {
        int r0 = bm + wm + mb * 16 + g;
        #pragma unroll
        for (int nb = 0; nb < 4; nb++) {
            int ccn = bn + wn + nb * 8 + 2 * t;
            *(float2*)(C + (size_t)r0 * ldc + ccn)       = make_float2(acc[mb][nb][0], acc[mb][nb][1]);
            *(float2*)(C + (size_t)(r0 + 8) * ldc + ccn) = make_float2(acc[mb][nb][2], acc[mb][nb][3]);
        }
    }
}

// ============================================================================
// fp16-split flash attention (3-term), ldmatrix fragments, cp.async K/V pipe
// ============================================================================
#define AP 68
#define QH_OFF 0
#define QL_OFF (QH_OFF + 64*AP)
#define KH_OFF (QL_OFF + 64*AP)
#define KL_OFF (KH_OFF + 128*AP)
#define VH_OFF (KL_OFF + 128*AP)
#define VL_OFF (VH_OFF + 128*AP)
#define PH_OFF (VL_OFF + 128*AP)
#define PL_OFF (PH_OFF + 64*AP)
#define ST_OFF (PL_OFF + 64*AP)
#define FA_SMEM_BYTES ((ST_OFF + 64*3 + 4*64*2) * 4)   // 211712 B

__global__ __launch_bounds__(256) void flash_attn_h3(
    const __half* __restrict__ Qh_g, const __half* __restrict__ Ql_g,
    const __half* __restrict__ Kh_g, const __half* __restrict__ Kl_g,
    const __half* __restrict__ Vh_g, const __half* __restrict__ Vl_g,
    __half* __restrict__ Oh_g)
{
    extern __shared__ uint32_t su[];
    const uint32_t sb = s2u(su);
    uint32_t* Ph = su + PH_OFF;
    uint32_t* Pl = su + PL_OFF;
    float* m_s  = (float*)(su + ST_OFF);
    float* l_s  = m_s + 64;
    float* rs_s = l_s + 64;
    float* pmax = rs_s + 64;
    float* psum = pmax + 4*64;

    const int tid = threadIdx.x, lane = tid & 31, w = tid >> 5;
    const int qt = blockIdx.x, h = blockIdx.y, b = blockIdx.z;
    const int gq = h >> 2;
    const int q0 = qt * 64;
    const int wm = (w & 1) * 32;
    const int wn = (w >> 1) * 32;
    const int g = lane >> 2, t = lane & 3;

    const int vm = tid >> 7;
    const int t128 = tid & 127;
    const int qr = t128 >> 4, qc = t128 & 15;

    // ldmatrix per-lane base addresses (row stride 272 B; 8-row offsets distinct mod 128B)
    const int arow = wm + ((lane >> 3) & 1) * 8 + (lane & 7);
    const uint32_t aBase = sb + arow * 272 + (lane >> 4) * 16;   // + region byte offset
    const int brow = wn + (lane >> 4) * 8 + (lane & 7);
    const uint32_t bBase = sb + brow * 272 + ((lane >> 3) & 1) * 16;

    auto issueK = [&](int s0k) {
        const __half* src = (vm ? Kl_g : Kh_g) + (size_t)(b*T_ + s0k + qr) * KVD_ + gq*HD_ + qc*8;
        uint32_t dst = sb + (uint32_t)(KH_OFF + vm*(128*AP))*4 + qr*272 + qc*16;
        #pragma unroll
        for (int i = 0; i < 16; i++)
            CP16(dst + i*8*272, src + (size_t)(8*i) * KVD_);
    };
    auto issueV = [&](int s0v) {
        const __half* src = (vm ? Vl_g : Vh_g) + ((size_t)(b*KV_ + gq)*HD_ + qr) * T_ + s0v + qc*8;
        uint32_t dst = sb + (uint32_t)(VH_OFF + vm*(128*AP))*4 + qr*272 + qc*16;
        #pragma unroll
        for (int i = 0; i < 16; i++)
            CP16(dst + i*8*272, src + (size_t)(8*i) * T_);
    };

    {
        const __half* src = (vm ? Ql_g : Qh_g) + (size_t)(b*T_ + q0 + qr) * D_ + h*HD_ + qc*8;
        uint32_t dst = sb + (uint32_t)(QH_OFF + vm*(64*AP))*4 + qr*272 + qc*16;
        #pragma unroll
        for (int i = 0; i < 8; i++)
            CP16(dst + i*8*272, src + (size_t)(8*i) * D_);
        issueK(0);
    }
    CPC;
    issueV(0);
    CPC;

    if (tid < 64) { m_s[tid] = -INFINITY; l_s[tid] = 0.f; }

    float acc[2][4][4];
    #pragma unroll
    for (int mb = 0; mb < 2; mb++)
        #pragma unroll
        for (int nb = 0; nb < 4; nb++)
            #pragma unroll
            for (int i = 0; i < 4; i++) acc[mb][nb][i] = 0.f;

    for (int it = 0; it < 16; it++) {
        CPW1;
        __syncthreads();

        // ---- S = Q K^T ----
        float sfr[2][4][4];
        #pragma unroll
        for (int mb = 0; mb < 2; mb++)
            #pragma unroll
            for (int nb = 0; nb < 4; nb++)
                #pragma unroll
                for (int i = 0; i < 4; i++) sfr[mb][nb][i] = 0.f;

        #pragma unroll
        for (int k16 = 0; k16 < 8; k16++) {
            uint32_t ah[2][4], al[2][4], bh[4][2], bl[4][2];
            #pragma unroll
            for (int mb = 0; mb < 2; mb++) {
                LDSM4(ah[mb][0], ah[mb][1], ah[mb][2], ah[mb][3],
                      aBase + QH_OFF*4 + mb*16*272 + k16*32);
                LDSM4(al[mb][0], al[mb][1], al[mb][2], al[mb][3],
                      aBase + QL_OFF*4 + mb*16*272 + k16*32);
            }
            #pragma unroll
            for (int nbp = 0; nbp < 2; nbp++) {
                LDSM4(bh[2*nbp][0], bh[2*nbp][1], bh[2*nbp+1][0], bh[2*nbp+1][1],
                      bBase + KH_OFF*4 + nbp*16*272 + k16*32);
                LDSM4(bl[2*nbp][0], bl[2*nbp][1], bl[2*nbp+1][0], bl[2*nbp+1][1],
                      bBase + KL_OFF*4 + nbp*16*272 + k16*32);
            }
            #pragma unroll
            for (int nb = 0; nb < 4; nb++)
                #pragma unroll
                for (int mb = 0; mb < 2; mb++) {
                    mma_f16(sfr[mb][nb], ah[mb], bh[nb]);
                    mma_f16(sfr[mb][nb], ah[mb], bl[nb]);
                    mma_f16(sfr[mb][nb], al[mb], bh[nb]);
                }
        }

        // ---- row max ----
        #pragma unroll
        for (int mb = 0; mb < 2; mb++) {
            float m0 = -INFINITY, m1 = -INFINITY;
            #pragma unroll
            for (int nb = 0; nb < 4; nb++) {
                m0 = fmaxf(m0, fmaxf(sfr[mb][nb][0], sfr[mb][nb][1]));
                m1 = fmaxf(m1, fmaxf(sfr[mb][nb][2], sfr[mb][nb][3]));
            }
            m0 = fmaxf(m0, __shfl_xor_sync(0xffffffffu, m0, 1));
            m0 = fmaxf(m0, __shfl_xor_sync(0xffffffffu, m0, 2));
            m1 = fmaxf(m1, __shfl_xor_sync(0xffffffffu, m1, 1));
            m1 = fmaxf(m1, __shfl_xor_sync(0xffffffffu, m1, 2));
            if (t == 0) {
                pmax[(w>>1)*64 + wm + mb*16 + g    ] = m0;
                pmax[(w>>1)*64 + wm + mb*16 + g + 8] = m1;
            }
        }
        __syncthreads();

        if (it + 1 < 16) issueK((it + 1) * 128);
        CPC;

        if (tid < 64) {
            int r = tid;
            float mt = fmaxf(fmaxf(pmax[r], pmax[64+r]), fmaxf(pmax[128+r], pmax[192+r]));
            float m_old = m_s[r];
            float m_new = fmaxf(m_old, mt);
            float rs = __expf(m_old - m_new);
            rs_s[r] = rs; m_s[r] = m_new; l_s[r] *= rs;
        }
        __syncthreads();

        // ---- exp, P->smem split, partial sums; rescale acc ----
        float ps[2][2] = {{0.f,0.f},{0.f,0.f}};
        #pragma unroll
        for (int mb = 0; mb < 2; mb++) {
            int row0 = wm + mb*16 + g;
            float m0 = m_s[row0], m1 = m_s[row0 + 8];
            #pragma unroll
            for (int nb = 0; nb < 4; nb++) {
                int pp = (wn >> 1) + nb*4 + t;
                float p0 = __expf(sfr[mb][nb][0] - m0);
                float p1 = __expf(sfr[mb][nb][1] - m0);
                float p2 = __expf(sfr[mb][nb][2] - m1);
                float p3 = __expf(sfr[mb][nb][3] - m1);
                ps[mb][0] += p0 + p1;
                ps[mb][1] += p2 + p3;
                uint32_t hh, ll;
                cvt2(p0, p1, hh, ll);
                Ph[row0*AP + pp] = hh; Pl[row0*AP + pp] = ll;
                cvt2(p2, p3, hh, ll);
                Ph[(row0+8)*AP + pp] = hh; Pl[(row0+8)*AP + pp] = ll;
            }
            ps[mb][0] += __shfl_xor_sync(0xffffffffu, ps[mb][0], 1);
            ps[mb][0] += __shfl_xor_sync(0xffffffffu, ps[mb][0], 2);
            ps[mb][1] += __shfl_xor_sync(0xffffffffu, ps[mb][1], 1);
            ps[mb][1] += __shfl_xor_sync(0xffffffffu, ps[mb][1], 2);
            if (t == 0) {
                psum[(w>>1)*64 + wm + mb*16 + g    ] = ps[mb][0];
                psum[(w>>1)*64 + wm + mb*16 + g + 8] = ps[mb][1];
            }
        }
        #pragma unroll
        for (int mb = 0; mb < 2; mb++) {
            int row0 = wm + mb*16 + g;
            float r0 = rs_s[row0], r1 = rs_s[row0 + 8];
            #pragma unroll
            for (int nb = 0; nb < 4; nb++) {
                acc[mb][nb][0] *= r0; acc[mb][nb][1] *= r0;
                acc[mb][nb][2] *= r1; acc[mb][nb][3] *= r1;
            }
        }
        if (it < 15) { CPW1; } else { CPW0; }
        __syncthreads();
        if (tid < 64)
            l_s[tid] += psum[tid] + psum[64+tid] + psum[128+tid] + psum[192+tid];

        // ---- O += P V ----
        #pragma unroll
        for (int k16 = 0; k16 < 8; k16++) {
            uint32_t ah[2][4], al[2][4], bh[4][2], bl[4][2];
            #pragma unroll
            for (int mb = 0; mb < 2; mb++) {
                LDSM4(ah[mb][0], ah[mb][1], ah[mb][2], ah[mb][3],
                      aBase + PH_OFF*4 + mb*16*272 + k16*32);
                LDSM4(al[mb][0], al[mb][1], al[mb][2], al[mb][3],
                      aBase + PL_OFF*4 + mb*16*272 + k16*32);
            }
            #pragma unroll
            for (int nbp = 0; nbp < 2; nbp++) {
                LDSM4(bh[2*nbp][0], bh[2*nbp][1], bh[2*nbp+1][0], bh[2*nbp+1][1],
                      bBase + VH_OFF*4 + nbp*16*272 + k16*32);
                LDSM4(bl[2*nbp][0], bl[2*nbp][1], bl[2*nbp+1][0], bl[2*nbp+1][1],
                      bBase + VL_OFF*4 + nbp*16*272 + k16*32);
            }
            #pragma unroll
            for (int nb = 0; nb < 4; nb++)
                #pragma unroll
                for (int mb = 0; mb < 2; mb++) {
                    mma_f16(acc[mb][nb], ah[mb], bh[nb]);
                    mma_f16(acc[mb][nb], ah[mb], bl[nb]);
                    mma_f16(acc[mb][nb], al[mb], bh[nb]);
                }
        }
        __syncthreads();

        if (it + 1 < 16) issueV((it + 1) * 128);
        CPC;
    }

    // ---- epilogue ----
    #pragma unroll
    for (int mb = 0; mb < 2; mb++) {
        int row0 = wm + mb*16 + g;
        float inv0 = 1.0f / l_s[row0];
        float inv1 = 1.0f / l_s[row0 + 8];
        #pragma unroll
        for (int nb = 0; nb < 4; nb++) {
            int col = h*HD_ + wn + nb*8 + 2*t;
            size_t o0 = (size_t)(b*T_ + q0 + row0) * D_ + col;
            size_t o1 = (size_t)(b*T_ + q0 + row0 + 8) * D_ + col;
            *(uint32_t*)(Oh_g + o0) = cvth(acc[mb][nb][0]*inv0, acc[mb][nb][1]*inv0);
            *(uint32_t*)(Oh_g + o1) = cvth(acc[mb][nb][2]*inv1, acc[mb][nb][3]*inv1);
        }
    }
}

// ---------------- launch ------------------------------------------------------
extern "C" void kernel_launch(void* const* d_in, const int* in_sizes, int n_in,
                              void* d_out, int out_size)
{
    const float* x  = (const float*)d_in[0];
    const float* wq = (const float*)d_in[1];
    const float* wk = (const float*)d_in[2];
    const float* wv = (const float*)d_in[3];
    const float* wo = (const float*)d_in[4];
    float* out = (float*)d_out;

    float *pQKV;
    __half *pXh, *pW3h, *pW3l, *pWoh, *pWol;
    __half *pQh, *pQl, *pKh, *pKl, *pVth, *pVtl, *pOh;
    cudaGetSymbolAddress((void**)&pQKV, g_QKVf);
    cudaGetSymbolAddress((void**)&pXh, g_Xh);
    cudaGetSymbolAddress((void**)&pW3h, g_W3h); cudaGetSymbolAddress((void**)&pW3l, g_W3l);
    cudaGetSymbolAddress((void**)&pWoh, g_Woh); cudaGetSymbolAddress((void**)&pWol, g_Wol);
    cudaGetSymbolAddress((void**)&pQh, g_Qh);   cudaGetSymbolAddress((void**)&pQl, g_Ql);
    cudaGetSymbolAddress((void**)&pKh, g_Kh2);  cudaGetSymbolAddress((void**)&pKl, g_Kl2);
    cudaGetSymbolAddress((void**)&pVth, g_Vth); cudaGetSymbolAddress((void**)&pVtl, g_Vtl);
    cudaGetSymbolAddress((void**)&pOh, g_Oh);

    cudaFuncSetAttribute(gemm_2t, cudaFuncAttributeMaxDynamicSharedMemorySize, G2_BYTES);
    cudaFuncSetAttribute(flash_attn_h3, cudaFuncAttributeMaxDynamicSharedMemorySize, FA_SMEM_BYTES);

    split_hi<<<(M_*D_/4)/256, 256>>>(x, pXh, M_*D_/4);
    split_f32<<<(D_*D_/4)/256,   256>>>(wq, pW3h,                      pW3l,                      D_*D_/4);
    split_f32<<<(KVD_*D_/4)/256, 256>>>(wk, pW3h + (size_t)2048*2048,  pW3l + (size_t)2048*2048,  KVD_*D_/4);
    split_f32<<<(KVD_*D_/4)/256, 256>>>(wv, pW3h + (size_t)2560*2048,  pW3l + (size_t)2560*2048,  KVD_*D_/4);
    split_f32<<<(D_*D_/4)/256,   256>>>(wo, pWoh, pWol, D_*D_/4);

    gemm_2t<<<dim3(NQKV/128, M_/128), 256, G2_BYTES>>>(pXh, pW3h, pW3l, pQKV, NQKV, D_);

    const float scale = 0.08838834764831845f;
    rope_split<<<(M_*H_*32)/256,  256>>>(pQKV, pQh, pQl, H_,  scale, NQKV, 0,    M_*H_*32);
    rope_split<<<(M_*KV_*32)/256, 256>>>(pQKV, pKh, pKl, KV_, 1.0f,  NQKV, 2048, M_*KV_*32);
    vtrans_split<<<dim3(T_/32, KVD_/32, B_), dim3(32, 8)>>>(pQKV, pVth, pVtl);

    flash_attn_h3<<<dim3(T_/64, H_, B_), 256, FA_SMEM_BYTES>>>(
        pQh, pQl, pKh, pKl, pVth, pVtl, pOh);

    gemm_2t<<<dim3(D_/128, M_/128), 256, G2_BYTES>>>(pOh, pWoh, pWol, out, D_, D_);
}